// round 13
// baseline (speedup 1.0000x reference)
#include <cuda_runtime.h>
#include <cuda_fp16.h>
#include <cstdint>

#define N_NODES 50000
#define N_EDGES 800000
#define F_IN    128
#define HID     256

// ---------------- scratch (device globals; no allocation allowed) ----------------
// INVARIANT: g_deg == 0 at kernel_launch entry (zero-init at load; scan1 re-zeros
// after consuming it, so every graph replay sees zeros again).
__device__ int    g_deg[N_NODES];
__device__ int    g_off[N_NODES + 1];
__device__ int    g_csr[N_EDGES];
__device__ int    g_bsum[256];
__device__ __half g_xh   [(size_t)N_NODES * F_IN];   // fp16 x
__device__ __half g_h1h  [(size_t)N_NODES * HID];    // fp16 h1
__device__ __half g_agg1h[(size_t)N_NODES * F_IN];   // fp16 agg1
__device__ __half g_agg2h[(size_t)N_NODES * HID];    // fp16 agg2
__device__ __half g_wrh  [196608];                   // fp16 W1l|W1r|W2l|W2r

#define W1L_OFF 0
#define W1R_OFF 32768
#define W2L_OFF 65536
#define W2R_OFF 131072

// ---------------- prep (x+weights -> fp16) fused with edge count ----------------
#define XN4 ((N_NODES * F_IN) / 4)      // 1,600,000
#define WN4 (196608 / 4)                // 49,152
#define EN4 (N_EDGES / 4)               // 200,000
__global__ void prep_count(const float* __restrict__ x,
                           const float* __restrict__ w1l, const float* __restrict__ w1r,
                           const float* __restrict__ w2l, const float* __restrict__ w2r,
                           const int* __restrict__ dst) {
    int i = blockIdx.x * blockDim.x + threadIdx.x;
    if (i < XN4) {
        float4 v = reinterpret_cast<const float4*>(x)[i];
        __half2 h0 = __floats2half2_rn(v.x, v.y);
        __half2 h1 = __floats2half2_rn(v.z, v.w);
        uint2 hu;
        hu.x = *reinterpret_cast<uint32_t*>(&h0);
        hu.y = *reinterpret_cast<uint32_t*>(&h1);
        reinterpret_cast<uint2*>(g_xh)[i] = hu;
        return;
    }
    int j = i - XN4;
    if (j < WN4) {
        int e = j * 4;
        const float* s;
        if      (e < W1R_OFF) s = w1l + (e - W1L_OFF);
        else if (e < W2L_OFF) s = w1r + (e - W1R_OFF);
        else if (e < W2R_OFF) s = w2l + (e - W2L_OFF);
        else                  s = w2r + (e - W2R_OFF);
        float4 v = *reinterpret_cast<const float4*>(s);
        __half2 h0 = __floats2half2_rn(v.x, v.y);
        __half2 h1 = __floats2half2_rn(v.z, v.w);
        uint2 hu;
        hu.x = *reinterpret_cast<uint32_t*>(&h0);
        hu.y = *reinterpret_cast<uint32_t*>(&h1);
        reinterpret_cast<uint2*>(g_wrh)[j] = hu;
        return;
    }
    int t = j - WN4;
    if (t >= EN4) return;
    int4 d = *reinterpret_cast<const int4*>(dst + t * 4);   // N_EDGES % 4 == 0
    atomicAdd(&g_deg[d.x], 1);
    atomicAdd(&g_deg[d.y], 1);
    atomicAdd(&g_deg[d.z], 1);
    atomicAdd(&g_deg[d.w], 1);
}

#define SCAN_BLOCKS 196
__device__ __forceinline__ int warp_incl_scan(int v, int lane) {
    #pragma unroll
    for (int o = 1; o < 32; o <<= 1) {
        int t = __shfl_up_sync(0xffffffffu, v, o);
        if (lane >= o) v += t;
    }
    return v;
}

__global__ void scan1_kernel() {   // local exclusive scan + block sums; re-zeros g_deg
    __shared__ int ws[8];
    int tid = threadIdx.x, lane = tid & 31, w = tid >> 5;
    int i = blockIdx.x * 256 + tid;
    int v = (i < N_NODES) ? g_deg[i] : 0;
    if (i < N_NODES) g_deg[i] = 0;            // restore invariant for next replay
    int inc = warp_incl_scan(v, lane);
    if (lane == 31) ws[w] = inc;
    __syncthreads();
    if (w == 0) {
        int t = (lane < 8) ? ws[lane] : 0;
        t = warp_incl_scan(t, lane);
        if (lane < 8) ws[lane] = t;
    }
    __syncthreads();
    int base = (w > 0) ? ws[w - 1] : 0;
    if (i < N_NODES) g_off[i] = base + inc - v;
    if (tid == 255) g_bsum[blockIdx.x] = ws[7];
}

__global__ void scan2_kernel() {   // merged spine-reduce + add-back
    __shared__ int ws[8];
    int tid = threadIdx.x, lane = tid & 31, w = tid >> 5;
    int bid = blockIdx.x;
    int v = (tid < bid) ? g_bsum[tid] : 0;
    #pragma unroll
    for (int o = 16; o > 0; o >>= 1) v += __shfl_xor_sync(0xffffffffu, v, o);
    if (lane == 0) ws[w] = v;
    __syncthreads();
    int base = ws[0] + ws[1] + ws[2] + ws[3] + ws[4] + ws[5] + ws[6] + ws[7];
    int i = bid * 256 + tid;
    if (i < N_NODES) g_off[i] += base;
    if (bid == SCAN_BLOCKS - 1 && tid == 0)
        g_off[N_NODES] = base + g_bsum[SCAN_BLOCKS - 1];
}

// fill uses g_off itself as the insertion cursor (shifted-offset trick):
// afterward g_off[d] == original g_off[d+1], so node n's segment is
// [ (n==0 ? 0 : g_off[n-1]), g_off[n] ).
__global__ void fill_kernel(const int* __restrict__ src, const int* __restrict__ dst) {
    int t = blockIdx.x * blockDim.x + threadIdx.x;
    int e0 = t * 4;
    if (e0 >= N_EDGES) return;
    int4 d = *reinterpret_cast<const int4*>(dst + e0);
    int4 s = *reinterpret_cast<const int4*>(src + e0);
    g_csr[atomicAdd(&g_off[d.x], 1)] = s.x;
    g_csr[atomicAdd(&g_off[d.y], 1)] = s.y;
    g_csr[atomicAdd(&g_off[d.z], 1)] = s.z;
    g_csr[atomicAdd(&g_off[d.w], 1)] = s.w;
}

// ---------------- mean aggregation (fp16 gather -> fp16 out) ----------------
// SL=1: warp per node, uint2 (8B) lane loads, F=128.
// SL=2: warp per node, uint4 (16B) lane loads, F=256.
// Segment bounds per shifted-offset convention (see fill_kernel).
template <int SL>
__global__ void agg_kernel_h(const __half* __restrict__ feat, __half* __restrict__ out) {
    constexpr int F = SL * 128;
    int node = blockIdx.x * (blockDim.x >> 5) + (threadIdx.x >> 5);
    if (node >= N_NODES) return;
    int lane = threadIdx.x & 31;
    int col = lane * (4 * SL);     // 4 or 8 halfs per lane

    float a[4][4 * SL];
    #pragma unroll
    for (int k = 0; k < 4; k++)
        #pragma unroll
        for (int q = 0; q < 4 * SL; q++) a[k][q] = 0.f;

    int s = (node == 0) ? 0 : g_off[node - 1];
    int e = g_off[node];
    int i = s;
    for (; i + 3 < e; i += 4) {
        int idx[4];
        #pragma unroll
        for (int k = 0; k < 4; k++) idx[k] = g_csr[i + k];
        #pragma unroll
        for (int k = 0; k < 4; k++) {
            if (SL == 1) {
                uint2 u = *reinterpret_cast<const uint2*>(feat + (size_t)idx[k] * F + col);
                float2 f0 = __half22float2(*reinterpret_cast<__half2*>(&u.x));
                float2 f1 = __half22float2(*reinterpret_cast<__half2*>(&u.y));
                a[k][0] += f0.x; a[k][1] += f0.y; a[k][2] += f1.x; a[k][3] += f1.y;
            } else {
                uint4 u = *reinterpret_cast<const uint4*>(feat + (size_t)idx[k] * F + col);
                float2 f0 = __half22float2(*reinterpret_cast<__half2*>(&u.x));
                float2 f1 = __half22float2(*reinterpret_cast<__half2*>(&u.y));
                float2 f2 = __half22float2(*reinterpret_cast<__half2*>(&u.z));
                float2 f3 = __half22float2(*reinterpret_cast<__half2*>(&u.w));
                a[k][0] += f0.x; a[k][1] += f0.y; a[k][2] += f1.x; a[k][3] += f1.y;
                a[k][4] += f2.x; a[k][5] += f2.y; a[k][6] += f3.x; a[k][7] += f3.y;
            }
        }
    }
    for (; i < e; i++) {
        int s0 = g_csr[i];
        if (SL == 1) {
            uint2 u = *reinterpret_cast<const uint2*>(feat + (size_t)s0 * F + col);
            float2 f0 = __half22float2(*reinterpret_cast<__half2*>(&u.x));
            float2 f1 = __half22float2(*reinterpret_cast<__half2*>(&u.y));
            a[0][0] += f0.x; a[0][1] += f0.y; a[0][2] += f1.x; a[0][3] += f1.y;
        } else {
            uint4 u = *reinterpret_cast<const uint4*>(feat + (size_t)s0 * F + col);
            float2 f0 = __half22float2(*reinterpret_cast<__half2*>(&u.x));
            float2 f1 = __half22float2(*reinterpret_cast<__half2*>(&u.y));
            float2 f2 = __half22float2(*reinterpret_cast<__half2*>(&u.z));
            float2 f3 = __half22float2(*reinterpret_cast<__half2*>(&u.w));
            a[0][0] += f0.x; a[0][1] += f0.y; a[0][2] += f1.x; a[0][3] += f1.y;
            a[0][4] += f2.x; a[0][5] += f2.y; a[0][6] += f3.x; a[0][7] += f3.y;
        }
    }
    float inv = (e > s) ? 1.0f / (float)(e - s) : 0.0f;
    if (SL == 1) {
        __half2 o0 = __floats2half2_rn((a[0][0] + a[1][0] + a[2][0] + a[3][0]) * inv,
                                       (a[0][1] + a[1][1] + a[2][1] + a[3][1]) * inv);
        __half2 o1 = __floats2half2_rn((a[0][2] + a[1][2] + a[2][2] + a[3][2]) * inv,
                                       (a[0][3] + a[1][3] + a[2][3] + a[3][3]) * inv);
        uint2 ou;
        ou.x = *reinterpret_cast<uint32_t*>(&o0);
        ou.y = *reinterpret_cast<uint32_t*>(&o1);
        *reinterpret_cast<uint2*>(out + (size_t)node * F + col) = ou;
    } else {
        uint4 ou;
        #pragma unroll
        for (int p = 0; p < 4; p++) {
            __half2 h = __floats2half2_rn(
                (a[0][2 * p] + a[1][2 * p] + a[2][2 * p] + a[3][2 * p]) * inv,
                (a[0][2 * p + 1] + a[1][2 * p + 1] + a[2][2 * p + 1] + a[3][2 * p + 1]) * inv);
            (&ou.x)[p] = *reinterpret_cast<uint32_t*>(&h);
        }
        *reinterpret_cast<uint4*>(out + (size_t)node * F + col) = ou;
    }
}

// ======================= fp16 m16n8k16 dual GEMM (+fused heads) =======================
#define GBM 128
#define GBN 256
#define GBK 32               // halfs per chunk
#define SPAD 20              // smem row stride in 32-bit words (16 data + 4 pad)
#define GTHREADS 512
#define NSTAGE 3

#define A_WORDS (GBM * SPAD)                   // 2560
#define B_WORDS (GBN * SPAD)                   // 5120
#define STAGE_WORDS (A_WORDS + B_WORDS)        // 7680
#define WH_WORDS 1792
#define PART_WORDS (4 * 128 * 7)
#define GEMM_SMEM_BYTES  (NSTAGE * STAGE_WORDS * 4)                            // 92160
#define GEMM2_SMEM_BYTES ((NSTAGE * STAGE_WORDS + WH_WORDS + PART_WORDS) * 4)  // 113664

__device__ __forceinline__ void mma_f16(float* d, const uint32_t* a, const uint32_t* b,
                                        const float* c) {
    asm volatile(
        "mma.sync.aligned.m16n8k16.row.col.f32.f16.f16.f32 "
        "{%0,%1,%2,%3}, {%4,%5,%6,%7}, {%8,%9}, {%10,%11,%12,%13};"
        : "=f"(d[0]), "=f"(d[1]), "=f"(d[2]), "=f"(d[3])
        : "r"(a[0]), "r"(a[1]), "r"(a[2]), "r"(a[3]),
          "r"(b[0]), "r"(b[1]),
          "f"(c[0]), "f"(c[1]), "f"(c[2]), "f"(c[3]));
}

__device__ __forceinline__ void cp16(uint32_t dst, const void* src, bool ok) {
    int sz = ok ? 16 : 0;
    asm volatile("cp.async.cg.shared.global [%0], [%1], 16, %2;"
                 :: "r"(dst), "l"(src), "r"(sz));
}
#define CP_COMMIT() asm volatile("cp.async.commit_group;" ::: "memory")
#define CP_WAIT(n)  asm volatile("cp.async.wait_group %0;" :: "n"(n) : "memory")

template <bool RELU, bool HEADS, bool STOREF, bool STOREH>
__global__ __launch_bounds__(GTHREADS)
void gemm_h(const __half* __restrict__ A1, const __half* __restrict__ B1, int K1,
            const __half* __restrict__ A2, const __half* __restrict__ B2, int K2,
            const float* __restrict__ bias, float* __restrict__ C, int M,
            __half* __restrict__ Ch,
            const float* __restrict__ Wh1, const float* __restrict__ bh1,
            const float* __restrict__ Wh2, const float* __restrict__ bh2,
            float* __restrict__ out1, float* __restrict__ out2) {
    extern __shared__ float gsm[];
    uint32_t sbase;
    asm("{ .reg .u64 t; cvta.to.shared.u64 t, %1; cvt.u32.u64 %0, t; }"
        : "=r"(sbase) : "l"(gsm));

    int tid  = threadIdx.x;
    int wid  = tid >> 5;
    int lane = tid & 31;
    int wm   = wid & 3;
    int wn   = wid >> 2;
    int g    = lane >> 2;
    int tg   = lane & 3;

    int m0 = blockIdx.x * GBM;

    float* whs  = gsm + NSTAGE * STAGE_WORDS;
    float* part = whs + WH_WORDS;
    if (HEADS) {
        for (int idx = tid; idx < WH_WORDS; idx += GTHREADS) {
            int o = idx >> 8, cc = idx & 255;
            whs[idx] = (o < 4) ? Wh1[o * 256 + cc] : Wh2[(o - 4) * 256 + cc];
        }
    }

    const int NC1 = K1 / GBK;
    const int NC  = NC1 + K2 / GBK;

    float acc[2][8][4];
    #pragma unroll
    for (int i = 0; i < 2; i++)
        #pragma unroll
        for (int j = 0; j < 8; j++)
            #pragma unroll
            for (int q = 0; q < 4; q++) acc[i][j][q] = 0.f;

    auto stage = [&](int c, int buf) {
        const __half* A; const __half* B; int K, k0;
        if (c < NC1) { A = A1; B = B1; K = K1; k0 = c * GBK; }
        else         { A = A2; B = B2; K = K2; k0 = (c - NC1) * GBK; }
        uint32_t abase = sbase + (buf * STAGE_WORDS) * 4;
        uint32_t bbase = abase + A_WORDS * 4;
        {
            int row = tid >> 2;
            int q   = tid & 3;
            cp16(abase + (row * SPAD + q * 4) * 4,
                 A + (size_t)(m0 + row) * K + k0 + q * 8,
                 (m0 + row) < M);
        }
        #pragma unroll
        for (int l = 0; l < 2; l++) {
            int idx = tid + l * GTHREADS;
            int row = idx >> 2;
            int q   = idx & 3;
            cp16(bbase + (row * SPAD + q * 4) * 4,
                 B + (size_t)row * K + k0 + q * 8, true);
        }
    };

    stage(0, 0); CP_COMMIT();
    stage(1, 1); CP_COMMIT();

    const uint32_t* usm = reinterpret_cast<const uint32_t*>(gsm);
    int buf = 0;

    for (int c = 0; c < NC; c++) {
        CP_WAIT(1);
        __syncthreads();

        const uint32_t* As = usm + buf * STAGE_WORDS;
        const uint32_t* Bs = As + A_WORDS;

        #pragma unroll
        for (int k16 = 0; k16 < 2; k16++) {
            int w0 = k16 * 8 + tg;
            uint32_t af[2][4], bf[8][2];
            #pragma unroll
            for (int i = 0; i < 2; i++) {
                int m = wm * 32 + i * 16 + g;
                af[i][0] = As[m * SPAD + w0];
                af[i][1] = As[(m + 8) * SPAD + w0];
                af[i][2] = As[m * SPAD + w0 + 4];
                af[i][3] = As[(m + 8) * SPAD + w0 + 4];
            }
            #pragma unroll
            for (int j = 0; j < 8; j++) {
                int n = wn * 64 + j * 8 + g;
                bf[j][0] = Bs[n * SPAD + w0];
                bf[j][1] = Bs[n * SPAD + w0 + 4];
            }
            #pragma unroll
            for (int i = 0; i < 2; i++)
                #pragma unroll
                for (int j = 0; j < 8; j++)
                    mma_f16(acc[i][j], af[i], bf[j], acc[i][j]);
        }

        if (c + 2 < NC) {
            int nb = buf + 2; if (nb >= NSTAGE) nb -= NSTAGE;
            stage(c + 2, nb);
            CP_COMMIT();
        } else {
            CP_COMMIT();
        }
        buf = (buf + 1 == NSTAGE) ? 0 : buf + 1;
    }

    // ---- epilogue ----
    float hs[4][7];
    if (HEADS) {
        #pragma unroll
        for (int sl = 0; sl < 4; sl++)
            #pragma unroll
            for (int o = 0; o < 7; o++) hs[sl][o] = 0.f;
    }

    #pragma unroll
    for (int i = 0; i < 2; i++) {
        int m = m0 + wm * 32 + i * 16 + g;
        bool ok0 = (m < M), ok1 = (m + 8 < M);
        #pragma unroll
        for (int j = 0; j < 8; j++) {
            int n = wn * 64 + j * 8 + 2 * tg;
            float bx = bias[n], by = bias[n + 1];
            float v0 = acc[i][j][0] + bx, v1 = acc[i][j][1] + by;
            float w0 = acc[i][j][2] + bx, w1 = acc[i][j][3] + by;
            if (RELU) {
                v0 = fmaxf(v0, 0.f); v1 = fmaxf(v1, 0.f);
                w0 = fmaxf(w0, 0.f); w1 = fmaxf(w1, 0.f);
            }
            if (STOREF) {
                if (ok0) *reinterpret_cast<float2*>(C + (size_t)m * 256 + n) = make_float2(v0, v1);
                if (ok1) *reinterpret_cast<float2*>(C + (size_t)(m + 8) * 256 + n) = make_float2(w0, w1);
            }
            if (STOREH) {
                if (ok0) *reinterpret_cast<__half2*>(Ch + (size_t)m * 256 + n) = __floats2half2_rn(v0, v1);
                if (ok1) *reinterpret_cast<__half2*>(Ch + (size_t)(m + 8) * 256 + n) = __floats2half2_rn(w0, w1);
            }
            if (HEADS) {
                #pragma unroll
                for (int o = 0; o < 7; o++) {
                    float wa = whs[o * 256 + n], wb = whs[o * 256 + n + 1];
                    if (ok0) hs[i * 2 + 0][o] += v0 * wa + v1 * wb;
                    if (ok1) hs[i * 2 + 1][o] += w0 * wa + w1 * wb;
                }
            }
        }
    }

    if (HEADS) {
        #pragma unroll
        for (int sl = 0; sl < 4; sl++)
            #pragma unroll
            for (int o = 0; o < 7; o++) {
                float v = hs[sl][o];
                v += __shfl_xor_sync(0xffffffffu, v, 1);
                v += __shfl_xor_sync(0xffffffffu, v, 2);
                hs[sl][o] = v;
            }
        if (tg == 0) {
            #pragma unroll
            for (int sl = 0; sl < 4; sl++) {
                int i = sl >> 1, h = sl & 1;
                int row = wm * 32 + i * 16 + g + h * 8;
                #pragma unroll
                for (int o = 0; o < 7; o++)
                    part[(wn * 128 + row) * 7 + o] = hs[sl][o];
            }
        }
        __syncthreads();
        if (tid < 128) {
            int m = m0 + tid;
            if (m < M) {
                #pragma unroll
                for (int o = 0; o < 7; o++) {
                    float v = part[(0 * 128 + tid) * 7 + o] + part[(1 * 128 + tid) * 7 + o]
                            + part[(2 * 128 + tid) * 7 + o] + part[(3 * 128 + tid) * 7 + o];
                    if (o < 4) out1[(size_t)m * 4 + o] = v + bh1[o];
                    else       out2[(size_t)m * 3 + (o - 4)] = v + bh2[o - 4];
                }
            }
        }
    }
}

// ---------------- launch ----------------
extern "C" void kernel_launch(void* const* d_in, const int* in_sizes, int n_in,
                              void* d_out, int out_size) {
    const float* x   = (const float*)d_in[0];
    const int*   ei  = (const int*)  d_in[1];
    const float* W1l = (const float*)d_in[2];
    const float* b1l = (const float*)d_in[3];
    const float* W1r = (const float*)d_in[4];
    const float* W2l = (const float*)d_in[5];
    const float* b2l = (const float*)d_in[6];
    const float* W2r = (const float*)d_in[7];
    const float* Wh1 = (const float*)d_in[8];
    const float* bh1 = (const float*)d_in[9];
    const float* Wh2 = (const float*)d_in[10];
    const float* bh2 = (const float*)d_in[11];

    float* out  = (float*)d_out;
    float* out1 = out;                                  // [N,4]
    float* out2 = out + (size_t)N_NODES * 4;            // [N,3]
    float* hout = out + (size_t)N_NODES * 7;            // [N,256]

    const int* src = ei;             // edge_index[0]
    const int* dst = ei + N_EDGES;   // edge_index[1]

    void *p_xh, *p_h1h, *p_agg1h, *p_agg2h, *p_wrh;
    cudaGetSymbolAddress(&p_xh,    g_xh);
    cudaGetSymbolAddress(&p_h1h,   g_h1h);
    cudaGetSymbolAddress(&p_agg1h, g_agg1h);
    cudaGetSymbolAddress(&p_agg2h, g_agg2h);
    cudaGetSymbolAddress(&p_wrh,   g_wrh);
    const __half* wrh = (const __half*)p_wrh;

    cudaFuncSetAttribute(gemm_h<true, false, false, true>,
                         cudaFuncAttributeMaxDynamicSharedMemorySize, GEMM_SMEM_BYTES);
    cudaFuncSetAttribute(gemm_h<false, true, true, false>,
                         cudaFuncAttributeMaxDynamicSharedMemorySize, GEMM2_SMEM_BYTES);

    prep_count<<<(XN4 + WN4 + EN4 + 255) / 256, 256>>>(x, W1l, W1r, W2l, W2r, dst);
    scan1_kernel<<<SCAN_BLOCKS, 256>>>();
    scan2_kernel<<<SCAN_BLOCKS, 256>>>();
    fill_kernel<<<(N_EDGES / 4 + 255) / 256, 256>>>(src, dst);

    int gtiles = (N_NODES + GBM - 1) / GBM;   // 391

    // layer 1: h1 = relu(agg1 @ W1l^T + x @ W1r^T + b1l)  [h1 stored fp16 only]
    agg_kernel_h<1><<<(N_NODES + 7) / 8, 256>>>((const __half*)p_xh, (__half*)p_agg1h);
    gemm_h<true, false, false, true><<<gtiles, GTHREADS, GEMM_SMEM_BYTES>>>(
        (const __half*)p_agg1h, wrh + W1L_OFF, F_IN, (const __half*)p_xh, wrh + W1R_OFF, F_IN,
        b1l, nullptr, N_NODES, (__half*)p_h1h,
        nullptr, nullptr, nullptr, nullptr, nullptr, nullptr);

    // layer 2 + heads: hout = agg2 @ W2l^T + h1 @ W2r^T + b2l; out1/out2 fused
    agg_kernel_h<2><<<(N_NODES + 7) / 8, 256>>>((const __half*)p_h1h, (__half*)p_agg2h);
    gemm_h<false, true, true, false><<<gtiles, GTHREADS, GEMM2_SMEM_BYTES>>>(
        (const __half*)p_agg2h, wrh + W2L_OFF, HID, (const __half*)p_h1h, wrh + W2R_OFF, HID,
        b2l, hout, N_NODES, nullptr,
        Wh1, bh1, Wh2, bh2, out1, out2);
}

// round 14
// speedup vs baseline: 1.0218x; 1.0218x over previous
#include <cuda_runtime.h>
#include <cuda_fp16.h>
#include <cstdint>

#define N_NODES 50000
#define N_EDGES 800000
#define F_IN    128
#define HID     256

// ---------------- scratch (device globals; no allocation allowed) ----------------
__device__ int    g_deg[N_NODES];
__device__ int    g_off[N_NODES + 1];
__device__ int    g_cur[N_NODES];
__device__ int    g_csr[N_EDGES];
__device__ int    g_bsum[256];
__device__ __half g_xh   [(size_t)N_NODES * F_IN];   // fp16 x
__device__ __half g_h1h  [(size_t)N_NODES * HID];    // fp16 h1
__device__ __half g_agg1h[(size_t)N_NODES * F_IN];   // fp16 agg1
__device__ __half g_agg2h[(size_t)N_NODES * HID];    // fp16 agg2
__device__ __half g_wrh  [196608];                   // fp16 W1l|W1r|W2l|W2r

#define W1L_OFF 0
#define W1R_OFF 32768
#define W2L_OFF 65536
#define W2R_OFF 131072

// ---------------- zero deg+cur in one launch ----------------
__global__ void zero_kernel() {
    int i = blockIdx.x * blockDim.x + threadIdx.x;
    if (i < N_NODES) { g_deg[i] = 0; g_cur[i] = 0; }
}

// ---------------- prep (x+weights -> fp16) fused with edge count (8 edges/thread) ----------------
#define XN4 ((N_NODES * F_IN) / 4)      // 1,600,000
#define WN4 (196608 / 4)                // 49,152
#define EN8 (N_EDGES / 8)               // 100,000
__global__ void prep_count(const float* __restrict__ x,
                           const float* __restrict__ w1l, const float* __restrict__ w1r,
                           const float* __restrict__ w2l, const float* __restrict__ w2r,
                           const int* __restrict__ dst) {
    int i = blockIdx.x * blockDim.x + threadIdx.x;
    if (i < XN4) {
        float4 v = reinterpret_cast<const float4*>(x)[i];
        __half2 h0 = __floats2half2_rn(v.x, v.y);
        __half2 h1 = __floats2half2_rn(v.z, v.w);
        uint2 hu;
        hu.x = *reinterpret_cast<uint32_t*>(&h0);
        hu.y = *reinterpret_cast<uint32_t*>(&h1);
        reinterpret_cast<uint2*>(g_xh)[i] = hu;
        return;
    }
    int j = i - XN4;
    if (j < WN4) {
        int e = j * 4;
        const float* s;
        if      (e < W1R_OFF) s = w1l + (e - W1L_OFF);
        else if (e < W2L_OFF) s = w1r + (e - W1R_OFF);
        else if (e < W2R_OFF) s = w2l + (e - W2L_OFF);
        else                  s = w2r + (e - W2R_OFF);
        float4 v = *reinterpret_cast<const float4*>(s);
        __half2 h0 = __floats2half2_rn(v.x, v.y);
        __half2 h1 = __floats2half2_rn(v.z, v.w);
        uint2 hu;
        hu.x = *reinterpret_cast<uint32_t*>(&h0);
        hu.y = *reinterpret_cast<uint32_t*>(&h1);
        reinterpret_cast<uint2*>(g_wrh)[j] = hu;
        return;
    }
    int t = j - WN4;
    if (t >= EN8) return;
    int e0 = t * 8;                                       // N_EDGES % 8 == 0
    int4 d0 = *reinterpret_cast<const int4*>(dst + e0);
    int4 d1 = *reinterpret_cast<const int4*>(dst + e0 + 4);
    atomicAdd(&g_deg[d0.x], 1); atomicAdd(&g_deg[d0.y], 1);
    atomicAdd(&g_deg[d0.z], 1); atomicAdd(&g_deg[d0.w], 1);
    atomicAdd(&g_deg[d1.x], 1); atomicAdd(&g_deg[d1.y], 1);
    atomicAdd(&g_deg[d1.z], 1); atomicAdd(&g_deg[d1.w], 1);
}

#define SCAN_BLOCKS 196
__device__ __forceinline__ int warp_incl_scan(int v, int lane) {
    #pragma unroll
    for (int o = 1; o < 32; o <<= 1) {
        int t = __shfl_up_sync(0xffffffffu, v, o);
        if (lane >= o) v += t;
    }
    return v;
}

__global__ void scan1_kernel() {
    __shared__ int ws[8];
    int tid = threadIdx.x, lane = tid & 31, w = tid >> 5;
    int i = blockIdx.x * 256 + tid;
    int v = (i < N_NODES) ? g_deg[i] : 0;
    int inc = warp_incl_scan(v, lane);
    if (lane == 31) ws[w] = inc;
    __syncthreads();
    if (w == 0) {
        int t = (lane < 8) ? ws[lane] : 0;
        t = warp_incl_scan(t, lane);
        if (lane < 8) ws[lane] = t;
    }
    __syncthreads();
    int base = (w > 0) ? ws[w - 1] : 0;
    if (i < N_NODES) g_off[i] = base + inc - v;
    if (tid == 255) g_bsum[blockIdx.x] = ws[7];
}

__global__ void scan2_kernel() {   // merged spine-reduce + add-back
    __shared__ int ws[8];
    int tid = threadIdx.x, lane = tid & 31, w = tid >> 5;
    int bid = blockIdx.x;
    int v = (tid < bid) ? g_bsum[tid] : 0;
    #pragma unroll
    for (int o = 16; o > 0; o >>= 1) v += __shfl_xor_sync(0xffffffffu, v, o);
    if (lane == 0) ws[w] = v;
    __syncthreads();
    int base = ws[0] + ws[1] + ws[2] + ws[3] + ws[4] + ws[5] + ws[6] + ws[7];
    int i = bid * 256 + tid;
    if (i < N_NODES) g_off[i] += base;
    if (bid == SCAN_BLOCKS - 1 && tid == 0)
        g_off[N_NODES] = base + g_bsum[SCAN_BLOCKS - 1];
}

__global__ void fill_kernel(const int* __restrict__ src, const int* __restrict__ dst) {
    int t = blockIdx.x * blockDim.x + threadIdx.x;
    int e0 = t * 8;
    if (e0 >= N_EDGES) return;
    int4 d0 = *reinterpret_cast<const int4*>(dst + e0);
    int4 d1 = *reinterpret_cast<const int4*>(dst + e0 + 4);
    int4 s0 = *reinterpret_cast<const int4*>(src + e0);
    int4 s1 = *reinterpret_cast<const int4*>(src + e0 + 4);
    g_csr[g_off[d0.x] + atomicAdd(&g_cur[d0.x], 1)] = s0.x;
    g_csr[g_off[d0.y] + atomicAdd(&g_cur[d0.y], 1)] = s0.y;
    g_csr[g_off[d0.z] + atomicAdd(&g_cur[d0.z], 1)] = s0.z;
    g_csr[g_off[d0.w] + atomicAdd(&g_cur[d0.w], 1)] = s0.w;
    g_csr[g_off[d1.x] + atomicAdd(&g_cur[d1.x], 1)] = s1.x;
    g_csr[g_off[d1.y] + atomicAdd(&g_cur[d1.y], 1)] = s1.y;
    g_csr[g_off[d1.z] + atomicAdd(&g_cur[d1.z], 1)] = s1.z;
    g_csr[g_off[d1.w] + atomicAdd(&g_cur[d1.w], 1)] = s1.w;
}

// ---------------- mean aggregation (fp16 gather -> fp16 out) ----------------
// SL=1: warp per node, uint2 (8B) lane loads, F=128.
// SL=2: warp per node, uint4 (16B) lane loads, F=256.
template <int SL>
__global__ void agg_kernel_h(const __half* __restrict__ feat, __half* __restrict__ out) {
    constexpr int F = SL * 128;
    int node = blockIdx.x * (blockDim.x >> 5) + (threadIdx.x >> 5);
    if (node >= N_NODES) return;
    int lane = threadIdx.x & 31;
    int col = lane * (4 * SL);     // 4 or 8 halfs per lane

    float a[4][4 * SL];
    #pragma unroll
    for (int k = 0; k < 4; k++)
        #pragma unroll
        for (int q = 0; q < 4 * SL; q++) a[k][q] = 0.f;

    int s = g_off[node], e = g_off[node + 1];
    int i = s;
    for (; i + 3 < e; i += 4) {
        int idx[4];
        #pragma unroll
        for (int k = 0; k < 4; k++) idx[k] = g_csr[i + k];
        #pragma unroll
        for (int k = 0; k < 4; k++) {
            if (SL == 1) {
                uint2 u = *reinterpret_cast<const uint2*>(feat + (size_t)idx[k] * F + col);
                float2 f0 = __half22float2(*reinterpret_cast<__half2*>(&u.x));
                float2 f1 = __half22float2(*reinterpret_cast<__half2*>(&u.y));
                a[k][0] += f0.x; a[k][1] += f0.y; a[k][2] += f1.x; a[k][3] += f1.y;
            } else {
                uint4 u = *reinterpret_cast<const uint4*>(feat + (size_t)idx[k] * F + col);
                float2 f0 = __half22float2(*reinterpret_cast<__half2*>(&u.x));
                float2 f1 = __half22float2(*reinterpret_cast<__half2*>(&u.y));
                float2 f2 = __half22float2(*reinterpret_cast<__half2*>(&u.z));
                float2 f3 = __half22float2(*reinterpret_cast<__half2*>(&u.w));
                a[k][0] += f0.x; a[k][1] += f0.y; a[k][2] += f1.x; a[k][3] += f1.y;
                a[k][4] += f2.x; a[k][5] += f2.y; a[k][6] += f3.x; a[k][7] += f3.y;
            }
        }
    }
    for (; i < e; i++) {
        int s0 = g_csr[i];
        if (SL == 1) {
            uint2 u = *reinterpret_cast<const uint2*>(feat + (size_t)s0 * F + col);
            float2 f0 = __half22float2(*reinterpret_cast<__half2*>(&u.x));
            float2 f1 = __half22float2(*reinterpret_cast<__half2*>(&u.y));
            a[0][0] += f0.x; a[0][1] += f0.y; a[0][2] += f1.x; a[0][3] += f1.y;
        } else {
            uint4 u = *reinterpret_cast<const uint4*>(feat + (size_t)s0 * F + col);
            float2 f0 = __half22float2(*reinterpret_cast<__half2*>(&u.x));
            float2 f1 = __half22float2(*reinterpret_cast<__half2*>(&u.y));
            float2 f2 = __half22float2(*reinterpret_cast<__half2*>(&u.z));
            float2 f3 = __half22float2(*reinterpret_cast<__half2*>(&u.w));
            a[0][0] += f0.x; a[0][1] += f0.y; a[0][2] += f1.x; a[0][3] += f1.y;
            a[0][4] += f2.x; a[0][5] += f2.y; a[0][6] += f3.x; a[0][7] += f3.y;
        }
    }
    float inv = (e > s) ? 1.0f / (float)(e - s) : 0.0f;
    if (SL == 1) {
        __half2 o0 = __floats2half2_rn((a[0][0] + a[1][0] + a[2][0] + a[3][0]) * inv,
                                       (a[0][1] + a[1][1] + a[2][1] + a[3][1]) * inv);
        __half2 o1 = __floats2half2_rn((a[0][2] + a[1][2] + a[2][2] + a[3][2]) * inv,
                                       (a[0][3] + a[1][3] + a[2][3] + a[3][3]) * inv);
        uint2 ou;
        ou.x = *reinterpret_cast<uint32_t*>(&o0);
        ou.y = *reinterpret_cast<uint32_t*>(&o1);
        *reinterpret_cast<uint2*>(out + (size_t)node * F + col) = ou;
    } else {
        uint4 ou;
        #pragma unroll
        for (int p = 0; p < 4; p++) {
            __half2 h = __floats2half2_rn(
                (a[0][2 * p] + a[1][2 * p] + a[2][2 * p] + a[3][2 * p]) * inv,
                (a[0][2 * p + 1] + a[1][2 * p + 1] + a[2][2 * p + 1] + a[3][2 * p + 1]) * inv);
            (&ou.x)[p] = *reinterpret_cast<uint32_t*>(&h);
        }
        *reinterpret_cast<uint4*>(out + (size_t)node * F + col) = ou;
    }
}

// ======================= fp16 m16n8k16 dual GEMM (+fused heads) =======================
#define GBM 128
#define GBN 256
#define GBK 32               // halfs per chunk
#define SPAD 20              // smem row stride in 32-bit words (16 data + 4 pad)
#define GTHREADS 512
#define NSTAGE 3

#define A_WORDS (GBM * SPAD)                   // 2560
#define B_WORDS (GBN * SPAD)                   // 5120
#define STAGE_WORDS (A_WORDS + B_WORDS)        // 7680
#define WH_WORDS 1792
#define PART_WORDS (4 * 128 * 7)
#define GEMM_SMEM_BYTES  (NSTAGE * STAGE_WORDS * 4)                            // 92160
#define GEMM2_SMEM_BYTES ((NSTAGE * STAGE_WORDS + WH_WORDS + PART_WORDS) * 4)  // 113664

__device__ __forceinline__ void mma_f16(float* d, const uint32_t* a, const uint32_t* b,
                                        const float* c) {
    asm volatile(
        "mma.sync.aligned.m16n8k16.row.col.f32.f16.f16.f32 "
        "{%0,%1,%2,%3}, {%4,%5,%6,%7}, {%8,%9}, {%10,%11,%12,%13};"
        : "=f"(d[0]), "=f"(d[1]), "=f"(d[2]), "=f"(d[3])
        : "r"(a[0]), "r"(a[1]), "r"(a[2]), "r"(a[3]),
          "r"(b[0]), "r"(b[1]),
          "f"(c[0]), "f"(c[1]), "f"(c[2]), "f"(c[3]));
}

__device__ __forceinline__ void cp16(uint32_t dst, const void* src, bool ok) {
    int sz = ok ? 16 : 0;
    asm volatile("cp.async.cg.shared.global [%0], [%1], 16, %2;"
                 :: "r"(dst), "l"(src), "r"(sz));
}
#define CP_COMMIT() asm volatile("cp.async.commit_group;" ::: "memory")
#define CP_WAIT(n)  asm volatile("cp.async.wait_group %0;" :: "n"(n) : "memory")

template <bool RELU, bool HEADS, bool STOREF, bool STOREH>
__global__ __launch_bounds__(GTHREADS)
void gemm_h(const __half* __restrict__ A1, const __half* __restrict__ B1, int K1,
            const __half* __restrict__ A2, const __half* __restrict__ B2, int K2,
            const float* __restrict__ bias, float* __restrict__ C, int M,
            __half* __restrict__ Ch,
            const float* __restrict__ Wh1, const float* __restrict__ bh1,
            const float* __restrict__ Wh2, const float* __restrict__ bh2,
            float* __restrict__ out1, float* __restrict__ out2) {
    extern __shared__ float gsm[];
    uint32_t sbase;
    asm("{ .reg .u64 t; cvta.to.shared.u64 t, %1; cvt.u32.u64 %0, t; }"
        : "=r"(sbase) : "l"(gsm));

    int tid  = threadIdx.x;
    int wid  = tid >> 5;
    int lane = tid & 31;
    int wm   = wid & 3;
    int wn   = wid >> 2;
    int g    = lane >> 2;
    int tg   = lane & 3;

    int m0 = blockIdx.x * GBM;

    float* whs  = gsm + NSTAGE * STAGE_WORDS;
    float* part = whs + WH_WORDS;
    if (HEADS) {
        for (int idx = tid; idx < WH_WORDS; idx += GTHREADS) {
            int o = idx >> 8, cc = idx & 255;
            whs[idx] = (o < 4) ? Wh1[o * 256 + cc] : Wh2[(o - 4) * 256 + cc];
        }
    }

    const int NC1 = K1 / GBK;
    const int NC  = NC1 + K2 / GBK;

    float acc[2][8][4];
    #pragma unroll
    for (int i = 0; i < 2; i++)
        #pragma unroll
        for (int j = 0; j < 8; j++)
            #pragma unroll
            for (int q = 0; q < 4; q++) acc[i][j][q] = 0.f;

    auto stage = [&](int c, int buf) {
        const __half* A; const __half* B; int K, k0;
        if (c < NC1) { A = A1; B = B1; K = K1; k0 = c * GBK; }
        else         { A = A2; B = B2; K = K2; k0 = (c - NC1) * GBK; }
        uint32_t abase = sbase + (buf * STAGE_WORDS) * 4;
        uint32_t bbase = abase + A_WORDS * 4;
        {
            int row = tid >> 2;
            int q   = tid & 3;
            cp16(abase + (row * SPAD + q * 4) * 4,
                 A + (size_t)(m0 + row) * K + k0 + q * 8,
                 (m0 + row) < M);
        }
        #pragma unroll
        for (int l = 0; l < 2; l++) {
            int idx = tid + l * GTHREADS;
            int row = idx >> 2;
            int q   = idx & 3;
            cp16(bbase + (row * SPAD + q * 4) * 4,
                 B + (size_t)row * K + k0 + q * 8, true);
        }
    };

    stage(0, 0); CP_COMMIT();
    stage(1, 1); CP_COMMIT();

    const uint32_t* usm = reinterpret_cast<const uint32_t*>(gsm);
    int buf = 0;

    for (int c = 0; c < NC; c++) {
        CP_WAIT(1);
        __syncthreads();

        const uint32_t* As = usm + buf * STAGE_WORDS;
        const uint32_t* Bs = As + A_WORDS;

        #pragma unroll
        for (int k16 = 0; k16 < 2; k16++) {
            int w0 = k16 * 8 + tg;
            uint32_t af[2][4], bf[8][2];
            #pragma unroll
            for (int i = 0; i < 2; i++) {
                int m = wm * 32 + i * 16 + g;
                af[i][0] = As[m * SPAD + w0];
                af[i][1] = As[(m + 8) * SPAD + w0];
                af[i][2] = As[m * SPAD + w0 + 4];
                af[i][3] = As[(m + 8) * SPAD + w0 + 4];
            }
            #pragma unroll
            for (int j = 0; j < 8; j++) {
                int n = wn * 64 + j * 8 + g;
                bf[j][0] = Bs[n * SPAD + w0];
                bf[j][1] = Bs[n * SPAD + w0 + 4];
            }
            #pragma unroll
            for (int i = 0; i < 2; i++)
                #pragma unroll
                for (int j = 0; j < 8; j++)
                    mma_f16(acc[i][j], af[i], bf[j], acc[i][j]);
        }

        if (c + 2 < NC) {
            int nb = buf + 2; if (nb >= NSTAGE) nb -= NSTAGE;
            stage(c + 2, nb);
            CP_COMMIT();
        } else {
            CP_COMMIT();
        }
        buf = (buf + 1 == NSTAGE) ? 0 : buf + 1;
    }

    // ---- epilogue ----
    float hs[4][7];
    if (HEADS) {
        #pragma unroll
        for (int sl = 0; sl < 4; sl++)
            #pragma unroll
            for (int o = 0; o < 7; o++) hs[sl][o] = 0.f;
    }

    #pragma unroll
    for (int i = 0; i < 2; i++) {
        int m = m0 + wm * 32 + i * 16 + g;
        bool ok0 = (m < M), ok1 = (m + 8 < M);
        #pragma unroll
        for (int j = 0; j < 8; j++) {
            int n = wn * 64 + j * 8 + 2 * tg;
            float bx = bias[n], by = bias[n + 1];
            float v0 = acc[i][j][0] + bx, v1 = acc[i][j][1] + by;
            float w0 = acc[i][j][2] + bx, w1 = acc[i][j][3] + by;
            if (RELU) {
                v0 = fmaxf(v0, 0.f); v1 = fmaxf(v1, 0.f);
                w0 = fmaxf(w0, 0.f); w1 = fmaxf(w1, 0.f);
            }
            if (STOREF) {
                if (ok0) *reinterpret_cast<float2*>(C + (size_t)m * 256 + n) = make_float2(v0, v1);
                if (ok1) *reinterpret_cast<float2*>(C + (size_t)(m + 8) * 256 + n) = make_float2(w0, w1);
            }
            if (STOREH) {
                if (ok0) *reinterpret_cast<__half2*>(Ch + (size_t)m * 256 + n) = __floats2half2_rn(v0, v1);
                if (ok1) *reinterpret_cast<__half2*>(Ch + (size_t)(m + 8) * 256 + n) = __floats2half2_rn(w0, w1);
            }
            if (HEADS) {
                #pragma unroll
                for (int o = 0; o < 7; o++) {
                    float wa = whs[o * 256 + n], wb = whs[o * 256 + n + 1];
                    if (ok0) hs[i * 2 + 0][o] += v0 * wa + v1 * wb;
                    if (ok1) hs[i * 2 + 1][o] += w0 * wa + w1 * wb;
                }
            }
        }
    }

    if (HEADS) {
        #pragma unroll
        for (int sl = 0; sl < 4; sl++)
            #pragma unroll
            for (int o = 0; o < 7; o++) {
                float v = hs[sl][o];
                v += __shfl_xor_sync(0xffffffffu, v, 1);
                v += __shfl_xor_sync(0xffffffffu, v, 2);
                hs[sl][o] = v;
            }
        if (tg == 0) {
            #pragma unroll
            for (int sl = 0; sl < 4; sl++) {
                int i = sl >> 1, h = sl & 1;
                int row = wm * 32 + i * 16 + g + h * 8;
                #pragma unroll
                for (int o = 0; o < 7; o++)
                    part[(wn * 128 + row) * 7 + o] = hs[sl][o];
            }
        }
        __syncthreads();
        if (tid < 128) {
            int m = m0 + tid;
            if (m < M) {
                #pragma unroll
                for (int o = 0; o < 7; o++) {
                    float v = part[(0 * 128 + tid) * 7 + o] + part[(1 * 128 + tid) * 7 + o]
                            + part[(2 * 128 + tid) * 7 + o] + part[(3 * 128 + tid) * 7 + o];
                    if (o < 4) out1[(size_t)m * 4 + o] = v + bh1[o];
                    else       out2[(size_t)m * 3 + (o - 4)] = v + bh2[o - 4];
                }
            }
        }
    }
}

// ---------------- launch ----------------
extern "C" void kernel_launch(void* const* d_in, const int* in_sizes, int n_in,
                              void* d_out, int out_size) {
    const float* x   = (const float*)d_in[0];
    const int*   ei  = (const int*)  d_in[1];
    const float* W1l = (const float*)d_in[2];
    const float* b1l = (const float*)d_in[3];
    const float* W1r = (const float*)d_in[4];
    const float* W2l = (const float*)d_in[5];
    const float* b2l = (const float*)d_in[6];
    const float* W2r = (const float*)d_in[7];
    const float* Wh1 = (const float*)d_in[8];
    const float* bh1 = (const float*)d_in[9];
    const float* Wh2 = (const float*)d_in[10];
    const float* bh2 = (const float*)d_in[11];

    float* out  = (float*)d_out;
    float* out1 = out;                                  // [N,4]
    float* out2 = out + (size_t)N_NODES * 4;            // [N,3]
    float* hout = out + (size_t)N_NODES * 7;            // [N,256]

    const int* src = ei;             // edge_index[0]
    const int* dst = ei + N_EDGES;   // edge_index[1]

    void *p_xh, *p_h1h, *p_agg1h, *p_agg2h, *p_wrh;
    cudaGetSymbolAddress(&p_xh,    g_xh);
    cudaGetSymbolAddress(&p_h1h,   g_h1h);
    cudaGetSymbolAddress(&p_agg1h, g_agg1h);
    cudaGetSymbolAddress(&p_agg2h, g_agg2h);
    cudaGetSymbolAddress(&p_wrh,   g_wrh);
    const __half* wrh = (const __half*)p_wrh;

    cudaFuncSetAttribute(gemm_h<true, false, false, true>,
                         cudaFuncAttributeMaxDynamicSharedMemorySize, GEMM_SMEM_BYTES);
    cudaFuncSetAttribute(gemm_h<false, true, true, false>,
                         cudaFuncAttributeMaxDynamicSharedMemorySize, GEMM2_SMEM_BYTES);

    zero_kernel<<<(N_NODES + 255) / 256, 256>>>();
    prep_count<<<(XN4 + WN4 + EN8 + 255) / 256, 256>>>(x, W1l, W1r, W2l, W2r, dst);
    scan1_kernel<<<SCAN_BLOCKS, 256>>>();
    scan2_kernel<<<SCAN_BLOCKS, 256>>>();
    fill_kernel<<<(N_EDGES / 8 + 255) / 256, 256>>>(src, dst);

    int gtiles = (N_NODES + GBM - 1) / GBM;   // 391

    // layer 1: h1 = relu(agg1 @ W1l^T + x @ W1r^T + b1l)  [h1 stored fp16 only]
    agg_kernel_h<1><<<(N_NODES + 7) / 8, 256>>>((const __half*)p_xh, (__half*)p_agg1h);
    gemm_h<true, false, false, true><<<gtiles, GTHREADS, GEMM_SMEM_BYTES>>>(
        (const __half*)p_agg1h, wrh + W1L_OFF, F_IN, (const __half*)p_xh, wrh + W1R_OFF, F_IN,
        b1l, nullptr, N_NODES, (__half*)p_h1h,
        nullptr, nullptr, nullptr, nullptr, nullptr, nullptr);

    // layer 2 + heads: hout = agg2 @ W2l^T + h1 @ W2r^T + b2l; out1/out2 fused
    agg_kernel_h<2><<<(N_NODES + 7) / 8, 256>>>((const __half*)p_h1h, (__half*)p_agg2h);
    gemm_h<false, true, true, false><<<gtiles, GTHREADS, GEMM2_SMEM_BYTES>>>(
        (const __half*)p_agg2h, wrh + W2L_OFF, HID, (const __half*)p_h1h, wrh + W2R_OFF, HID,
        b2l, hout, N_NODES, nullptr,
        Wh1, bh1, Wh2, bh2, out1, out2);
}

// round 15
// speedup vs baseline: 1.0564x; 1.0339x over previous
#include <cuda_runtime.h>
#include <cuda_fp16.h>
#include <cstdint>

#define N_NODES 50000
#define N_EDGES 800000
#define F_IN    128
#define HID     256

// ---------------- scratch (device globals; no allocation allowed) ----------------
__device__ int    g_deg[N_NODES];
__device__ int    g_off[N_NODES + 1];
__device__ int    g_cur[N_NODES];
__device__ int    g_csr[N_EDGES];
__device__ int    g_bsum[256];
__device__ __half g_xh   [(size_t)N_NODES * F_IN];   // fp16 x
__device__ __half g_h1h  [(size_t)N_NODES * HID];    // fp16 h1
__device__ __half g_agg1h[(size_t)N_NODES * F_IN];   // fp16 agg1
__device__ __half g_agg2h[(size_t)N_NODES * HID];    // fp16 agg2
__device__ __half g_wrh  [196608];                   // fp16 W1l|W1r|W2l|W2r

#define W1L_OFF 0
#define W1R_OFF 32768
#define W2L_OFF 65536
#define W2R_OFF 131072

// ---------------- zero deg+cur in one launch ----------------
__global__ void zero_kernel() {
    int i = blockIdx.x * blockDim.x + threadIdx.x;
    if (i < N_NODES) { g_deg[i] = 0; g_cur[i] = 0; }
}

// ---------------- prep (x+weights -> fp16) fused with edge count (8 edges/thread) ----------------
#define XN4 ((N_NODES * F_IN) / 4)      // 1,600,000
#define WN4 (196608 / 4)                // 49,152
#define EN8 (N_EDGES / 8)               // 100,000
__global__ void prep_count(const float* __restrict__ x,
                           const float* __restrict__ w1l, const float* __restrict__ w1r,
                           const float* __restrict__ w2l, const float* __restrict__ w2r,
                           const int* __restrict__ dst) {
    int i = blockIdx.x * blockDim.x + threadIdx.x;
    if (i < XN4) {
        float4 v = reinterpret_cast<const float4*>(x)[i];
        __half2 h0 = __floats2half2_rn(v.x, v.y);
        __half2 h1 = __floats2half2_rn(v.z, v.w);
        uint2 hu;
        hu.x = *reinterpret_cast<uint32_t*>(&h0);
        hu.y = *reinterpret_cast<uint32_t*>(&h1);
        reinterpret_cast<uint2*>(g_xh)[i] = hu;
        return;
    }
    int j = i - XN4;
    if (j < WN4) {
        int e = j * 4;
        const float* s;
        if      (e < W1R_OFF) s = w1l + (e - W1L_OFF);
        else if (e < W2L_OFF) s = w1r + (e - W1R_OFF);
        else if (e < W2R_OFF) s = w2l + (e - W2L_OFF);
        else                  s = w2r + (e - W2R_OFF);
        float4 v = *reinterpret_cast<const float4*>(s);
        __half2 h0 = __floats2half2_rn(v.x, v.y);
        __half2 h1 = __floats2half2_rn(v.z, v.w);
        uint2 hu;
        hu.x = *reinterpret_cast<uint32_t*>(&h0);
        hu.y = *reinterpret_cast<uint32_t*>(&h1);
        reinterpret_cast<uint2*>(g_wrh)[j] = hu;
        return;
    }
    int t = j - WN4;
    if (t >= EN8) return;
    int e0 = t * 8;                                       // N_EDGES % 8 == 0
    int4 d0 = *reinterpret_cast<const int4*>(dst + e0);
    int4 d1 = *reinterpret_cast<const int4*>(dst + e0 + 4);
    atomicAdd(&g_deg[d0.x], 1); atomicAdd(&g_deg[d0.y], 1);
    atomicAdd(&g_deg[d0.z], 1); atomicAdd(&g_deg[d0.w], 1);
    atomicAdd(&g_deg[d1.x], 1); atomicAdd(&g_deg[d1.y], 1);
    atomicAdd(&g_deg[d1.z], 1); atomicAdd(&g_deg[d1.w], 1);
}

#define SCAN_BLOCKS 196
__device__ __forceinline__ int warp_incl_scan(int v, int lane) {
    #pragma unroll
    for (int o = 1; o < 32; o <<= 1) {
        int t = __shfl_up_sync(0xffffffffu, v, o);
        if (lane >= o) v += t;
    }
    return v;
}

__global__ void scan1_kernel() {
    __shared__ int ws[8];
    int tid = threadIdx.x, lane = tid & 31, w = tid >> 5;
    int i = blockIdx.x * 256 + tid;
    int v = (i < N_NODES) ? g_deg[i] : 0;
    int inc = warp_incl_scan(v, lane);
    if (lane == 31) ws[w] = inc;
    __syncthreads();
    if (w == 0) {
        int t = (lane < 8) ? ws[lane] : 0;
        t = warp_incl_scan(t, lane);
        if (lane < 8) ws[lane] = t;
    }
    __syncthreads();
    int base = (w > 0) ? ws[w - 1] : 0;
    if (i < N_NODES) g_off[i] = base + inc - v;
    if (tid == 255) g_bsum[blockIdx.x] = ws[7];
}

__global__ void scan2_kernel() {   // merged spine-reduce + add-back
    __shared__ int ws[8];
    int tid = threadIdx.x, lane = tid & 31, w = tid >> 5;
    int bid = blockIdx.x;
    int v = (tid < bid) ? g_bsum[tid] : 0;
    #pragma unroll
    for (int o = 16; o > 0; o >>= 1) v += __shfl_xor_sync(0xffffffffu, v, o);
    if (lane == 0) ws[w] = v;
    __syncthreads();
    int base = ws[0] + ws[1] + ws[2] + ws[3] + ws[4] + ws[5] + ws[6] + ws[7];
    int i = bid * 256 + tid;
    if (i < N_NODES) g_off[i] += base;
    if (bid == SCAN_BLOCKS - 1 && tid == 0)
        g_off[N_NODES] = base + g_bsum[SCAN_BLOCKS - 1];
}

__global__ void fill_kernel(const int* __restrict__ src, const int* __restrict__ dst) {
    int t = blockIdx.x * blockDim.x + threadIdx.x;
    int e0 = t * 8;
    if (e0 >= N_EDGES) return;
    int4 d0 = *reinterpret_cast<const int4*>(dst + e0);
    int4 d1 = *reinterpret_cast<const int4*>(dst + e0 + 4);
    int4 s0 = *reinterpret_cast<const int4*>(src + e0);
    int4 s1 = *reinterpret_cast<const int4*>(src + e0 + 4);
    g_csr[g_off[d0.x] + atomicAdd(&g_cur[d0.x], 1)] = s0.x;
    g_csr[g_off[d0.y] + atomicAdd(&g_cur[d0.y], 1)] = s0.y;
    g_csr[g_off[d0.z] + atomicAdd(&g_cur[d0.z], 1)] = s0.z;
    g_csr[g_off[d0.w] + atomicAdd(&g_cur[d0.w], 1)] = s0.w;
    g_csr[g_off[d1.x] + atomicAdd(&g_cur[d1.x], 1)] = s1.x;
    g_csr[g_off[d1.y] + atomicAdd(&g_cur[d1.y], 1)] = s1.y;
    g_csr[g_off[d1.z] + atomicAdd(&g_cur[d1.z], 1)] = s1.z;
    g_csr[g_off[d1.w] + atomicAdd(&g_cur[d1.w], 1)] = s1.w;
}

// ---------------- mean aggregation (fp16 gather -> fp16 out) ----------------
template <int SL>
__global__ void agg_kernel_h(const __half* __restrict__ feat, __half* __restrict__ out) {
    constexpr int F = SL * 128;
    int node = blockIdx.x * (blockDim.x >> 5) + (threadIdx.x >> 5);
    if (node >= N_NODES) return;
    int lane = threadIdx.x & 31;
    int col = lane * (4 * SL);     // 4 or 8 halfs per lane

    float a[4][4 * SL];
    #pragma unroll
    for (int k = 0; k < 4; k++)
        #pragma unroll
        for (int q = 0; q < 4 * SL; q++) a[k][q] = 0.f;

    int s = g_off[node], e = g_off[node + 1];
    int i = s;
    for (; i + 3 < e; i += 4) {
        int idx[4];
        #pragma unroll
        for (int k = 0; k < 4; k++) idx[k] = g_csr[i + k];
        #pragma unroll
        for (int k = 0; k < 4; k++) {
            if (SL == 1) {
                uint2 u = *reinterpret_cast<const uint2*>(feat + (size_t)idx[k] * F + col);
                float2 f0 = __half22float2(*reinterpret_cast<__half2*>(&u.x));
                float2 f1 = __half22float2(*reinterpret_cast<__half2*>(&u.y));
                a[k][0] += f0.x; a[k][1] += f0.y; a[k][2] += f1.x; a[k][3] += f1.y;
            } else {
                uint4 u = *reinterpret_cast<const uint4*>(feat + (size_t)idx[k] * F + col);
                float2 f0 = __half22float2(*reinterpret_cast<__half2*>(&u.x));
                float2 f1 = __half22float2(*reinterpret_cast<__half2*>(&u.y));
                float2 f2 = __half22float2(*reinterpret_cast<__half2*>(&u.z));
                float2 f3 = __half22float2(*reinterpret_cast<__half2*>(&u.w));
                a[k][0] += f0.x; a[k][1] += f0.y; a[k][2] += f1.x; a[k][3] += f1.y;
                a[k][4] += f2.x; a[k][5] += f2.y; a[k][6] += f3.x; a[k][7] += f3.y;
            }
        }
    }
    for (; i < e; i++) {
        int s0 = g_csr[i];
        if (SL == 1) {
            uint2 u = *reinterpret_cast<const uint2*>(feat + (size_t)s0 * F + col);
            float2 f0 = __half22float2(*reinterpret_cast<__half2*>(&u.x));
            float2 f1 = __half22float2(*reinterpret_cast<__half2*>(&u.y));
            a[0][0] += f0.x; a[0][1] += f0.y; a[0][2] += f1.x; a[0][3] += f1.y;
        } else {
            uint4 u = *reinterpret_cast<const uint4*>(feat + (size_t)s0 * F + col);
            float2 f0 = __half22float2(*reinterpret_cast<__half2*>(&u.x));
            float2 f1 = __half22float2(*reinterpret_cast<__half2*>(&u.y));
            float2 f2 = __half22float2(*reinterpret_cast<__half2*>(&u.z));
            float2 f3 = __half22float2(*reinterpret_cast<__half2*>(&u.w));
            a[0][0] += f0.x; a[0][1] += f0.y; a[0][2] += f1.x; a[0][3] += f1.y;
            a[0][4] += f2.x; a[0][5] += f2.y; a[0][6] += f3.x; a[0][7] += f3.y;
        }
    }
    float inv = (e > s) ? 1.0f / (float)(e - s) : 0.0f;
    if (SL == 1) {
        __half2 o0 = __floats2half2_rn((a[0][0] + a[1][0] + a[2][0] + a[3][0]) * inv,
                                       (a[0][1] + a[1][1] + a[2][1] + a[3][1]) * inv);
        __half2 o1 = __floats2half2_rn((a[0][2] + a[1][2] + a[2][2] + a[3][2]) * inv,
                                       (a[0][3] + a[1][3] + a[2][3] + a[3][3]) * inv);
        uint2 ou;
        ou.x = *reinterpret_cast<uint32_t*>(&o0);
        ou.y = *reinterpret_cast<uint32_t*>(&o1);
        *reinterpret_cast<uint2*>(out + (size_t)node * F + col) = ou;
    } else {
        uint4 ou;
        #pragma unroll
        for (int p = 0; p < 4; p++) {
            __half2 h = __floats2half2_rn(
                (a[0][2 * p] + a[1][2 * p] + a[2][2 * p] + a[3][2 * p]) * inv,
                (a[0][2 * p + 1] + a[1][2 * p + 1] + a[2][2 * p + 1] + a[3][2 * p + 1]) * inv);
            (&ou.x)[p] = *reinterpret_cast<uint32_t*>(&h);
        }
        *reinterpret_cast<uint4*>(out + (size_t)node * F + col) = ou;
    }
}

// ======================= fp16 m16n8k16 dual GEMM (+fused heads, ldmatrix fragments) =======================
#define GBM 128
#define GBN 256
#define GBK 32               // halfs per chunk
#define SPAD 20              // smem row stride in 32-bit words (16 data + 4 pad)
#define GTHREADS 512
#define NSTAGE 3

#define A_WORDS (GBM * SPAD)                   // 2560
#define B_WORDS (GBN * SPAD)                   // 5120
#define STAGE_WORDS (A_WORDS + B_WORDS)        // 7680
#define WH_WORDS 1792
#define PART_WORDS (4 * 128 * 7)
#define GEMM_SMEM_BYTES  (NSTAGE * STAGE_WORDS * 4)                            // 92160
#define GEMM2_SMEM_BYTES ((NSTAGE * STAGE_WORDS + WH_WORDS + PART_WORDS) * 4)  // 113664

__device__ __forceinline__ void mma_f16(float* d, const uint32_t* a, const uint32_t* b,
                                        const float* c) {
    asm volatile(
        "mma.sync.aligned.m16n8k16.row.col.f32.f16.f16.f32 "
        "{%0,%1,%2,%3}, {%4,%5,%6,%7}, {%8,%9}, {%10,%11,%12,%13};"
        : "=f"(d[0]), "=f"(d[1]), "=f"(d[2]), "=f"(d[3])
        : "r"(a[0]), "r"(a[1]), "r"(a[2]), "r"(a[3]),
          "r"(b[0]), "r"(b[1]),
          "f"(c[0]), "f"(c[1]), "f"(c[2]), "f"(c[3]));
}

#define LDMX4(r0, r1, r2, r3, addr) \
    asm volatile("ldmatrix.sync.aligned.m8n8.x4.shared.b16 {%0,%1,%2,%3}, [%4];" \
        : "=r"(r0), "=r"(r1), "=r"(r2), "=r"(r3) : "r"(addr))

__device__ __forceinline__ void cp16(uint32_t dst, const void* src, bool ok) {
    int sz = ok ? 16 : 0;
    asm volatile("cp.async.cg.shared.global [%0], [%1], 16, %2;"
                 :: "r"(dst), "l"(src), "r"(sz));
}
#define CP_COMMIT() asm volatile("cp.async.commit_group;" ::: "memory")
#define CP_WAIT(n)  asm volatile("cp.async.wait_group %0;" :: "n"(n) : "memory")

template <bool RELU, bool HEADS, bool STOREF, bool STOREH>
__global__ __launch_bounds__(GTHREADS)
void gemm_h(const __half* __restrict__ A1, const __half* __restrict__ B1, int K1,
            const __half* __restrict__ A2, const __half* __restrict__ B2, int K2,
            const float* __restrict__ bias, float* __restrict__ C, int M,
            __half* __restrict__ Ch,
            const float* __restrict__ Wh1, const float* __restrict__ bh1,
            const float* __restrict__ Wh2, const float* __restrict__ bh2,
            float* __restrict__ out1, float* __restrict__ out2) {
    extern __shared__ float gsm[];
    uint32_t sbase;
    asm("{ .reg .u64 t; cvta.to.shared.u64 t, %1; cvt.u32.u64 %0, t; }"
        : "=r"(sbase) : "l"(gsm));

    int tid  = threadIdx.x;
    int wid  = tid >> 5;
    int lane = tid & 31;
    int wm   = wid & 3;
    int wn   = wid >> 2;
    int g    = lane >> 2;
    int tg   = lane & 3;

    int m0 = blockIdx.x * GBM;

    // ldmatrix lane addressing (bytes, relative to tile base at k-word 0):
    // quad 0..3 -> matrix 0..3; r = row within 8-row group.
    int quad = lane >> 3, r = lane & 7;
    // A tile (m16 x k16): mat0 rows m..m+7 k0, mat1 rows m+8.. k0, mat2 rows m.. k8, mat3 rows m+8.. k8
    uint32_t a_lane = (uint32_t)((((quad & 1) ? 8 : 0) + r) * SPAD * 4 + (quad >> 1) * 16);
    // B pair tile (n16 x k16): mat0 n..n+7 k0, mat1 n..n+7 k8, mat2 n+8.. k0, mat3 n+8.. k8
    uint32_t b_lane = (uint32_t)((((quad >> 1) ? 8 : 0) + r) * SPAD * 4 + (quad & 1) * 16);

    float* whs  = gsm + NSTAGE * STAGE_WORDS;
    float* part = whs + WH_WORDS;
    if (HEADS) {
        for (int idx = tid; idx < WH_WORDS; idx += GTHREADS) {
            int o = idx >> 8, cc = idx & 255;
            whs[idx] = (o < 4) ? Wh1[o * 256 + cc] : Wh2[(o - 4) * 256 + cc];
        }
    }

    const int NC1 = K1 / GBK;
    const int NC  = NC1 + K2 / GBK;

    float acc[2][8][4];
    #pragma unroll
    for (int i = 0; i < 2; i++)
        #pragma unroll
        for (int j = 0; j < 8; j++)
            #pragma unroll
            for (int q = 0; q < 4; q++) acc[i][j][q] = 0.f;

    auto stage = [&](int c, int buf) {
        const __half* A; const __half* B; int K, k0;
        if (c < NC1) { A = A1; B = B1; K = K1; k0 = c * GBK; }
        else         { A = A2; B = B2; K = K2; k0 = (c - NC1) * GBK; }
        uint32_t abase = sbase + (buf * STAGE_WORDS) * 4;
        uint32_t bbase = abase + A_WORDS * 4;
        {
            int row = tid >> 2;
            int q   = tid & 3;
            cp16(abase + (row * SPAD + q * 4) * 4,
                 A + (size_t)(m0 + row) * K + k0 + q * 8,
                 (m0 + row) < M);
        }
        #pragma unroll
        for (int l = 0; l < 2; l++) {
            int idx = tid + l * GTHREADS;
            int row = idx >> 2;
            int q   = idx & 3;
            cp16(bbase + (row * SPAD + q * 4) * 4,
                 B + (size_t)row * K + k0 + q * 8, true);
        }
    };

    stage(0, 0); CP_COMMIT();
    stage(1, 1); CP_COMMIT();

    int buf = 0;

    for (int c = 0; c < NC; c++) {
        CP_WAIT(1);
        __syncthreads();

        uint32_t abase = sbase + (buf * STAGE_WORDS) * 4;
        uint32_t bbase = abase + A_WORDS * 4;
        // per-warp tile bases (k-word 0 of this chunk)
        uint32_t a_tile = abase + (uint32_t)(wm * 32 * SPAD * 4) + a_lane;
        uint32_t b_tile = bbase + (uint32_t)(wn * 64 * SPAD * 4) + b_lane;

        #pragma unroll
        for (int k16 = 0; k16 < 2; k16++) {
            uint32_t koff = (uint32_t)(k16 * 32);   // 8 words = 32 bytes per k16 step
            uint32_t af[2][4], bf[8][2];
            #pragma unroll
            for (int i = 0; i < 2; i++) {
                LDMX4(af[i][0], af[i][1], af[i][2], af[i][3],
                      a_tile + (uint32_t)(i * 16 * SPAD * 4) + koff);
            }
            #pragma unroll
            for (int j2 = 0; j2 < 4; j2++) {
                LDMX4(bf[2 * j2][0], bf[2 * j2][1], bf[2 * j2 + 1][0], bf[2 * j2 + 1][1],
                      b_tile + (uint32_t)(j2 * 16 * SPAD * 4) + koff);
            }
            #pragma unroll
            for (int i = 0; i < 2; i++)
                #pragma unroll
                for (int j = 0; j < 8; j++)
                    mma_f16(acc[i][j], af[i], bf[j], acc[i][j]);
        }

        if (c + 2 < NC) {
            int nb = buf + 2; if (nb >= NSTAGE) nb -= NSTAGE;
            stage(c + 2, nb);
            CP_COMMIT();
        } else {
            CP_COMMIT();
        }
        buf = (buf + 1 == NSTAGE) ? 0 : buf + 1;
    }

    // ---- epilogue ----
    float hs[4][7];
    if (HEADS) {
        #pragma unroll
        for (int sl = 0; sl < 4; sl++)
            #pragma unroll
            for (int o = 0; o < 7; o++) hs[sl][o] = 0.f;
    }

    #pragma unroll
    for (int i = 0; i < 2; i++) {
        int m = m0 + wm * 32 + i * 16 + g;
        bool ok0 = (m < M), ok1 = (m + 8 < M);
        #pragma unroll
        for (int j = 0; j < 8; j++) {
            int n = wn * 64 + j * 8 + 2 * tg;
            float bx = bias[n], by = bias[n + 1];
            float v0 = acc[i][j][0] + bx, v1 = acc[i][j][1] + by;
            float w0 = acc[i][j][2] + bx, w1 = acc[i][j][3] + by;
            if (RELU) {
                v0 = fmaxf(v0, 0.f); v1 = fmaxf(v1, 0.f);
                w0 = fmaxf(w0, 0.f); w1 = fmaxf(w1, 0.f);
            }
            if (STOREF) {
                if (ok0) *reinterpret_cast<float2*>(C + (size_t)m * 256 + n) = make_float2(v0, v1);
                if (ok1) *reinterpret_cast<float2*>(C + (size_t)(m + 8) * 256 + n) = make_float2(w0, w1);
            }
            if (STOREH) {
                if (ok0) *reinterpret_cast<__half2*>(Ch + (size_t)m * 256 + n) = __floats2half2_rn(v0, v1);
                if (ok1) *reinterpret_cast<__half2*>(Ch + (size_t)(m + 8) * 256 + n) = __floats2half2_rn(w0, w1);
            }
            if (HEADS) {
                #pragma unroll
                for (int o = 0; o < 7; o++) {
                    float wa = whs[o * 256 + n], wb = whs[o * 256 + n + 1];
                    if (ok0) hs[i * 2 + 0][o] += v0 * wa + v1 * wb;
                    if (ok1) hs[i * 2 + 1][o] += w0 * wa + w1 * wb;
                }
            }
        }
    }

    if (HEADS) {
        #pragma unroll
        for (int sl = 0; sl < 4; sl++)
            #pragma unroll
            for (int o = 0; o < 7; o++) {
                float v = hs[sl][o];
                v += __shfl_xor_sync(0xffffffffu, v, 1);
                v += __shfl_xor_sync(0xffffffffu, v, 2);
                hs[sl][o] = v;
            }
        if (tg == 0) {
            #pragma unroll
            for (int sl = 0; sl < 4; sl++) {
                int i = sl >> 1, h = sl & 1;
                int row = wm * 32 + i * 16 + g + h * 8;
                #pragma unroll
                for (int o = 0; o < 7; o++)
                    part[(wn * 128 + row) * 7 + o] = hs[sl][o];
            }
        }
        __syncthreads();
        if (tid < 128) {
            int m = m0 + tid;
            if (m < M) {
                #pragma unroll
                for (int o = 0; o < 7; o++) {
                    float v = part[(0 * 128 + tid) * 7 + o] + part[(1 * 128 + tid) * 7 + o]
                            + part[(2 * 128 + tid) * 7 + o] + part[(3 * 128 + tid) * 7 + o];
                    if (o < 4) out1[(size_t)m * 4 + o] = v + bh1[o];
                    else       out2[(size_t)m * 3 + (o - 4)] = v + bh2[o - 4];
                }
            }
        }
    }
}

// ---------------- launch ----------------
extern "C" void kernel_launch(void* const* d_in, const int* in_sizes, int n_in,
                              void* d_out, int out_size) {
    const float* x   = (const float*)d_in[0];
    const int*   ei  = (const int*)  d_in[1];
    const float* W1l = (const float*)d_in[2];
    const float* b1l = (const float*)d_in[3];
    const float* W1r = (const float*)d_in[4];
    const float* W2l = (const float*)d_in[5];
    const float* b2l = (const float*)d_in[6];
    const float* W2r = (const float*)d_in[7];
    const float* Wh1 = (const float*)d_in[8];
    const float* bh1 = (const float*)d_in[9];
    const float* Wh2 = (const float*)d_in[10];
    const float* bh2 = (const float*)d_in[11];

    float* out  = (float*)d_out;
    float* out1 = out;                                  // [N,4]
    float* out2 = out + (size_t)N_NODES * 4;            // [N,3]
    float* hout = out + (size_t)N_NODES * 7;            // [N,256]

    const int* src = ei;             // edge_index[0]
    const int* dst = ei + N_EDGES;   // edge_index[1]

    void *p_xh, *p_h1h, *p_agg1h, *p_agg2h, *p_wrh;
    cudaGetSymbolAddress(&p_xh,    g_xh);
    cudaGetSymbolAddress(&p_h1h,   g_h1h);
    cudaGetSymbolAddress(&p_agg1h, g_agg1h);
    cudaGetSymbolAddress(&p_agg2h, g_agg2h);
    cudaGetSymbolAddress(&p_wrh,   g_wrh);
    const __half* wrh = (const __half*)p_wrh;

    cudaFuncSetAttribute(gemm_h<true, false, false, true>,
                         cudaFuncAttributeMaxDynamicSharedMemorySize, GEMM_SMEM_BYTES);
    cudaFuncSetAttribute(gemm_h<false, true, true, false>,
                         cudaFuncAttributeMaxDynamicSharedMemorySize, GEMM2_SMEM_BYTES);

    zero_kernel<<<(N_NODES + 255) / 256, 256>>>();
    prep_count<<<(XN4 + WN4 + EN8 + 255) / 256, 256>>>(x, W1l, W1r, W2l, W2r, dst);
    scan1_kernel<<<SCAN_BLOCKS, 256>>>();
    scan2_kernel<<<SCAN_BLOCKS, 256>>>();
    fill_kernel<<<(N_EDGES / 8 + 255) / 256, 256>>>(src, dst);

    int gtiles = (N_NODES + GBM - 1) / GBM;   // 391

    // layer 1: h1 = relu(agg1 @ W1l^T + x @ W1r^T + b1l)  [h1 stored fp16 only]
    agg_kernel_h<1><<<(N_NODES + 7) / 8, 256>>>((const __half*)p_xh, (__half*)p_agg1h);
    gemm_h<true, false, false, true><<<gtiles, GTHREADS, GEMM_SMEM_BYTES>>>(
        (const __half*)p_agg1h, wrh + W1L_OFF, F_IN, (const __half*)p_xh, wrh + W1R_OFF, F_IN,
        b1l, nullptr, N_NODES, (__half*)p_h1h,
        nullptr, nullptr, nullptr, nullptr, nullptr, nullptr);

    // layer 2 + heads: hout = agg2 @ W2l^T + h1 @ W2r^T + b2l; out1/out2 fused
    agg_kernel_h<2><<<(N_NODES + 7) / 8, 256>>>((const __half*)p_h1h, (__half*)p_agg2h);
    gemm_h<false, true, true, false><<<gtiles, GTHREADS, GEMM2_SMEM_BYTES>>>(
        (const __half*)p_agg2h, wrh + W2L_OFF, HID, (const __half*)p_h1h, wrh + W2R_OFF, HID,
        b2l, hout, N_NODES, nullptr,
        Wh1, bh1, Wh2, bh2, out1, out2);
}

// round 16
// speedup vs baseline: 1.0908x; 1.0326x over previous
#include <cuda_runtime.h>
#include <cuda_fp16.h>
#include <cstdint>

#define N_NODES 50000
#define N_EDGES 800000
#define F_IN    128
#define HID     256

// ---------------- scratch (device globals; no allocation allowed) ----------------
// INVARIANTS at kernel_launch entry (zero-init at load, restored each replay):
//   g_deg == 0  (scan1 re-zeros after reading)
//   g_cur == 0  (scan2 zeros alongside its add-back)
__device__ int    g_deg[N_NODES];
__device__ int    g_off[N_NODES + 1];
__device__ int    g_cur[N_NODES];
__device__ int    g_csr[N_EDGES];
__device__ int    g_bsum[256];
__device__ __half g_xh   [(size_t)N_NODES * F_IN];   // fp16 x
__device__ __half g_h1h  [(size_t)N_NODES * HID];    // fp16 h1
__device__ __half g_agg1h[(size_t)N_NODES * F_IN];   // fp16 agg1
__device__ __half g_agg2h[(size_t)N_NODES * HID];    // fp16 agg2
__device__ __half g_wrh  [196608];                   // fp16 W1l|W1r|W2l|W2r

#define W1L_OFF 0
#define W1R_OFF 32768
#define W2L_OFF 65536
#define W2R_OFF 131072

// ---------------- prep (x+weights -> fp16) fused with edge count (8 edges/thread) ----------------
#define XN4 ((N_NODES * F_IN) / 4)      // 1,600,000
#define WN4 (196608 / 4)                // 49,152
#define EN8 (N_EDGES / 8)               // 100,000
__global__ void prep_count(const float* __restrict__ x,
                           const float* __restrict__ w1l, const float* __restrict__ w1r,
                           const float* __restrict__ w2l, const float* __restrict__ w2r,
                           const int* __restrict__ dst) {
    int i = blockIdx.x * blockDim.x + threadIdx.x;
    if (i < XN4) {
        float4 v = reinterpret_cast<const float4*>(x)[i];
        __half2 h0 = __floats2half2_rn(v.x, v.y);
        __half2 h1 = __floats2half2_rn(v.z, v.w);
        uint2 hu;
        hu.x = *reinterpret_cast<uint32_t*>(&h0);
        hu.y = *reinterpret_cast<uint32_t*>(&h1);
        reinterpret_cast<uint2*>(g_xh)[i] = hu;
        return;
    }
    int j = i - XN4;
    if (j < WN4) {
        int e = j * 4;
        const float* s;
        if      (e < W1R_OFF) s = w1l + (e - W1L_OFF);
        else if (e < W2L_OFF) s = w1r + (e - W1R_OFF);
        else if (e < W2R_OFF) s = w2l + (e - W2L_OFF);
        else                  s = w2r + (e - W2R_OFF);
        float4 v = *reinterpret_cast<const float4*>(s);
        __half2 h0 = __floats2half2_rn(v.x, v.y);
        __half2 h1 = __floats2half2_rn(v.z, v.w);
        uint2 hu;
        hu.x = *reinterpret_cast<uint32_t*>(&h0);
        hu.y = *reinterpret_cast<uint32_t*>(&h1);
        reinterpret_cast<uint2*>(g_wrh)[j] = hu;
        return;
    }
    int t = j - WN4;
    if (t >= EN8) return;
    int e0 = t * 8;                                       // N_EDGES % 8 == 0
    int4 d0 = *reinterpret_cast<const int4*>(dst + e0);
    int4 d1 = *reinterpret_cast<const int4*>(dst + e0 + 4);
    atomicAdd(&g_deg[d0.x], 1); atomicAdd(&g_deg[d0.y], 1);
    atomicAdd(&g_deg[d0.z], 1); atomicAdd(&g_deg[d0.w], 1);
    atomicAdd(&g_deg[d1.x], 1); atomicAdd(&g_deg[d1.y], 1);
    atomicAdd(&g_deg[d1.z], 1); atomicAdd(&g_deg[d1.w], 1);
}

#define SCAN_BLOCKS 196
__device__ __forceinline__ int warp_incl_scan(int v, int lane) {
    #pragma unroll
    for (int o = 1; o < 32; o <<= 1) {
        int t = __shfl_up_sync(0xffffffffu, v, o);
        if (lane >= o) v += t;
    }
    return v;
}

__global__ void scan1_kernel() {   // local exclusive scan + block sums; re-zeros g_deg
    __shared__ int ws[8];
    int tid = threadIdx.x, lane = tid & 31, w = tid >> 5;
    int i = blockIdx.x * 256 + tid;
    int v = (i < N_NODES) ? g_deg[i] : 0;
    if (i < N_NODES) g_deg[i] = 0;
    int inc = warp_incl_scan(v, lane);
    if (lane == 31) ws[w] = inc;
    __syncthreads();
    if (w == 0) {
        int t = (lane < 8) ? ws[lane] : 0;
        t = warp_incl_scan(t, lane);
        if (lane < 8) ws[lane] = t;
    }
    __syncthreads();
    int base = (w > 0) ? ws[w - 1] : 0;
    if (i < N_NODES) g_off[i] = base + inc - v;
    if (tid == 255) g_bsum[blockIdx.x] = ws[7];
}

__global__ void scan2_kernel() {   // merged spine-reduce + add-back; zeros g_cur
    __shared__ int ws[8];
    int tid = threadIdx.x, lane = tid & 31, w = tid >> 5;
    int bid = blockIdx.x;
    int v = (tid < bid) ? g_bsum[tid] : 0;
    #pragma unroll
    for (int o = 16; o > 0; o >>= 1) v += __shfl_xor_sync(0xffffffffu, v, o);
    if (lane == 0) ws[w] = v;
    __syncthreads();
    int base = ws[0] + ws[1] + ws[2] + ws[3] + ws[4] + ws[5] + ws[6] + ws[7];
    int i = bid * 256 + tid;
    if (i < N_NODES) {
        g_off[i] += base;
        g_cur[i] = 0;
    }
    if (bid == SCAN_BLOCKS - 1 && tid == 0)
        g_off[N_NODES] = base + g_bsum[SCAN_BLOCKS - 1];
}

__global__ void fill_kernel(const int* __restrict__ src, const int* __restrict__ dst) {
    int t = blockIdx.x * blockDim.x + threadIdx.x;
    int e0 = t * 8;
    if (e0 >= N_EDGES) return;
    int4 d0 = *reinterpret_cast<const int4*>(dst + e0);
    int4 d1 = *reinterpret_cast<const int4*>(dst + e0 + 4);
    int4 s0 = *reinterpret_cast<const int4*>(src + e0);
    int4 s1 = *reinterpret_cast<const int4*>(src + e0 + 4);
    g_csr[g_off[d0.x] + atomicAdd(&g_cur[d0.x], 1)] = s0.x;
    g_csr[g_off[d0.y] + atomicAdd(&g_cur[d0.y], 1)] = s0.y;
    g_csr[g_off[d0.z] + atomicAdd(&g_cur[d0.z], 1)] = s0.z;
    g_csr[g_off[d0.w] + atomicAdd(&g_cur[d0.w], 1)] = s0.w;
    g_csr[g_off[d1.x] + atomicAdd(&g_cur[d1.x], 1)] = s1.x;
    g_csr[g_off[d1.y] + atomicAdd(&g_cur[d1.y], 1)] = s1.y;
    g_csr[g_off[d1.z] + atomicAdd(&g_cur[d1.z], 1)] = s1.z;
    g_csr[g_off[d1.w] + atomicAdd(&g_cur[d1.w], 1)] = s1.w;
}

// ---------------- mean aggregation (fp16 gather -> fp16 out) ----------------
template <int SL>
__global__ void agg_kernel_h(const __half* __restrict__ feat, __half* __restrict__ out) {
    constexpr int F = SL * 128;
    int node = blockIdx.x * (blockDim.x >> 5) + (threadIdx.x >> 5);
    if (node >= N_NODES) return;
    int lane = threadIdx.x & 31;
    int col = lane * (4 * SL);     // 4 or 8 halfs per lane

    float a[4][4 * SL];
    #pragma unroll
    for (int k = 0; k < 4; k++)
        #pragma unroll
        for (int q = 0; q < 4 * SL; q++) a[k][q] = 0.f;

    int s = g_off[node], e = g_off[node + 1];
    int i = s;
    for (; i + 3 < e; i += 4) {
        int idx[4];
        #pragma unroll
        for (int k = 0; k < 4; k++) idx[k] = g_csr[i + k];
        #pragma unroll
        for (int k = 0; k < 4; k++) {
            if (SL == 1) {
                uint2 u = *reinterpret_cast<const uint2*>(feat + (size_t)idx[k] * F + col);
                float2 f0 = __half22float2(*reinterpret_cast<__half2*>(&u.x));
                float2 f1 = __half22float2(*reinterpret_cast<__half2*>(&u.y));
                a[k][0] += f0.x; a[k][1] += f0.y; a[k][2] += f1.x; a[k][3] += f1.y;
            } else {
                uint4 u = *reinterpret_cast<const uint4*>(feat + (size_t)idx[k] * F + col);
                float2 f0 = __half22float2(*reinterpret_cast<__half2*>(&u.x));
                float2 f1 = __half22float2(*reinterpret_cast<__half2*>(&u.y));
                float2 f2 = __half22float2(*reinterpret_cast<__half2*>(&u.z));
                float2 f3 = __half22float2(*reinterpret_cast<__half2*>(&u.w));
                a[k][0] += f0.x; a[k][1] += f0.y; a[k][2] += f1.x; a[k][3] += f1.y;
                a[k][4] += f2.x; a[k][5] += f2.y; a[k][6] += f3.x; a[k][7] += f3.y;
            }
        }
    }
    for (; i < e; i++) {
        int s0 = g_csr[i];
        if (SL == 1) {
            uint2 u = *reinterpret_cast<const uint2*>(feat + (size_t)s0 * F + col);
            float2 f0 = __half22float2(*reinterpret_cast<__half2*>(&u.x));
            float2 f1 = __half22float2(*reinterpret_cast<__half2*>(&u.y));
            a[0][0] += f0.x; a[0][1] += f0.y; a[0][2] += f1.x; a[0][3] += f1.y;
        } else {
            uint4 u = *reinterpret_cast<const uint4*>(feat + (size_t)s0 * F + col);
            float2 f0 = __half22float2(*reinterpret_cast<__half2*>(&u.x));
            float2 f1 = __half22float2(*reinterpret_cast<__half2*>(&u.y));
            float2 f2 = __half22float2(*reinterpret_cast<__half2*>(&u.z));
            float2 f3 = __half22float2(*reinterpret_cast<__half2*>(&u.w));
            a[0][0] += f0.x; a[0][1] += f0.y; a[0][2] += f1.x; a[0][3] += f1.y;
            a[0][4] += f2.x; a[0][5] += f2.y; a[0][6] += f3.x; a[0][7] += f3.y;
        }
    }
    float inv = (e > s) ? 1.0f / (float)(e - s) : 0.0f;
    if (SL == 1) {
        __half2 o0 = __floats2half2_rn((a[0][0] + a[1][0] + a[2][0] + a[3][0]) * inv,
                                       (a[0][1] + a[1][1] + a[2][1] + a[3][1]) * inv);
        __half2 o1 = __floats2half2_rn((a[0][2] + a[1][2] + a[2][2] + a[3][2]) * inv,
                                       (a[0][3] + a[1][3] + a[2][3] + a[3][3]) * inv);
        uint2 ou;
        ou.x = *reinterpret_cast<uint32_t*>(&o0);
        ou.y = *reinterpret_cast<uint32_t*>(&o1);
        *reinterpret_cast<uint2*>(out + (size_t)node * F + col) = ou;
    } else {
        uint4 ou;
        #pragma unroll
        for (int p = 0; p < 4; p++) {
            __half2 h = __floats2half2_rn(
                (a[0][2 * p] + a[1][2 * p] + a[2][2 * p] + a[3][2 * p]) * inv,
                (a[0][2 * p + 1] + a[1][2 * p + 1] + a[2][2 * p + 1] + a[3][2 * p + 1]) * inv);
            (&ou.x)[p] = *reinterpret_cast<uint32_t*>(&h);
        }
        *reinterpret_cast<uint4*>(out + (size_t)node * F + col) = ou;
    }
}

// ======================= fp16 m16n8k16 dual GEMM (+fused heads, ldmatrix, BK=64) =======================
#define GBM 128
#define GBN 256
#define GBK 64               // halfs per chunk (128B rows)
#define SPAD 36              // smem row stride in 32-bit words (32 data + 4 pad)
#define GTHREADS 512
#define NSTAGE 3

#define A_WORDS (GBM * SPAD)                   // 4608
#define B_WORDS (GBN * SPAD)                   // 9216
#define STAGE_WORDS (A_WORDS + B_WORDS)        // 13824
#define WH_WORDS 1792
#define PART_WORDS (4 * 128 * 7)
#define GEMM_SMEM_BYTES  (NSTAGE * STAGE_WORDS * 4)                            // 165888
#define GEMM2_SMEM_BYTES ((NSTAGE * STAGE_WORDS + WH_WORDS + PART_WORDS) * 4)  // 187392

__device__ __forceinline__ void mma_f16(float* d, const uint32_t* a, const uint32_t* b,
                                        const float* c) {
    asm volatile(
        "mma.sync.aligned.m16n8k16.row.col.f32.f16.f16.f32 "
        "{%0,%1,%2,%3}, {%4,%5,%6,%7}, {%8,%9}, {%10,%11,%12,%13};"
        : "=f"(d[0]), "=f"(d[1]), "=f"(d[2]), "=f"(d[3])
        : "r"(a[0]), "r"(a[1]), "r"(a[2]), "r"(a[3]),
          "r"(b[0]), "r"(b[1]),
          "f"(c[0]), "f"(c[1]), "f"(c[2]), "f"(c[3]));
}

#define LDMX4(r0, r1, r2, r3, addr) \
    asm volatile("ldmatrix.sync.aligned.m8n8.x4.shared.b16 {%0,%1,%2,%3}, [%4];" \
        : "=r"(r0), "=r"(r1), "=r"(r2), "=r"(r3) : "r"(addr))

__device__ __forceinline__ void cp16(uint32_t dst, const void* src, bool ok) {
    int sz = ok ? 16 : 0;
    asm volatile("cp.async.cg.shared.global [%0], [%1], 16, %2;"
                 :: "r"(dst), "l"(src), "r"(sz));
}
#define CP_COMMIT() asm volatile("cp.async.commit_group;" ::: "memory")
#define CP_WAIT(n)  asm volatile("cp.async.wait_group %0;" :: "n"(n) : "memory")

template <bool RELU, bool HEADS, bool STOREF, bool STOREH>
__global__ __launch_bounds__(GTHREADS)
void gemm_h(const __half* __restrict__ A1, const __half* __restrict__ B1, int K1,
            const __half* __restrict__ A2, const __half* __restrict__ B2, int K2,
            const float* __restrict__ bias, float* __restrict__ C, int M,
            __half* __restrict__ Ch,
            const float* __restrict__ Wh1, const float* __restrict__ bh1,
            const float* __restrict__ Wh2, const float* __restrict__ bh2,
            float* __restrict__ out1, float* __restrict__ out2) {
    extern __shared__ float gsm[];
    uint32_t sbase;
    asm("{ .reg .u64 t; cvta.to.shared.u64 t, %1; cvt.u32.u64 %0, t; }"
        : "=r"(sbase) : "l"(gsm));

    int tid  = threadIdx.x;
    int wid  = tid >> 5;
    int lane = tid & 31;
    int wm   = wid & 3;
    int wn   = wid >> 2;
    int g    = lane >> 2;
    int tg   = lane & 3;

    int m0 = blockIdx.x * GBM;

    // ldmatrix lane addressing (bytes, relative to tile base at k-word 0):
    int quad = lane >> 3, r = lane & 7;
    // A (m16 x k16): mat0 m..+7 k0, mat1 m+8.. k0, mat2 m.. k8, mat3 m+8.. k8
    uint32_t a_lane = (uint32_t)((((quad & 1) ? 8 : 0) + r) * SPAD * 4 + (quad >> 1) * 16);
    // B pair (n16 x k16): mat0 n..+7 k0, mat1 n..+7 k8, mat2 n+8.. k0, mat3 n+8.. k8
    uint32_t b_lane = (uint32_t)((((quad >> 1) ? 8 : 0) + r) * SPAD * 4 + (quad & 1) * 16);

    float* whs  = gsm + NSTAGE * STAGE_WORDS;
    float* part = whs + WH_WORDS;
    if (HEADS) {
        for (int idx = tid; idx < WH_WORDS; idx += GTHREADS) {
            int o = idx >> 8, cc = idx & 255;
            whs[idx] = (o < 4) ? Wh1[o * 256 + cc] : Wh2[(o - 4) * 256 + cc];
        }
    }

    const int NC1 = K1 / GBK;
    const int NC  = NC1 + K2 / GBK;   // 4 (gemm1) or 8 (gemm2)

    float acc[2][8][4];
    #pragma unroll
    for (int i = 0; i < 2; i++)
        #pragma unroll
        for (int j = 0; j < 8; j++)
            #pragma unroll
            for (int q = 0; q < 4; q++) acc[i][j][q] = 0.f;

    // stage chunk c: A 128x64h (1024x16B -> 2/thread), B 256x64h (2048 -> 4/thread)
    auto stage = [&](int c, int buf) {
        const __half* A; const __half* B; int K, k0;
        if (c < NC1) { A = A1; B = B1; K = K1; k0 = c * GBK; }
        else         { A = A2; B = B2; K = K2; k0 = (c - NC1) * GBK; }
        uint32_t abase = sbase + (buf * STAGE_WORDS) * 4;
        uint32_t bbase = abase + A_WORDS * 4;
        #pragma unroll
        for (int l = 0; l < 2; l++) {
            int idx = tid + l * GTHREADS;
            int row = idx >> 3;
            int q   = idx & 7;          // 16B unit within 128B row
            cp16(abase + (row * SPAD + q * 4) * 4,
                 A + (size_t)(m0 + row) * K + k0 + q * 8,
                 (m0 + row) < M);
        }
        #pragma unroll
        for (int l = 0; l < 4; l++) {
            int idx = tid + l * GTHREADS;
            int row = idx >> 3;
            int q   = idx & 7;
            cp16(bbase + (row * SPAD + q * 4) * 4,
                 B + (size_t)row * K + k0 + q * 8, true);
        }
    };

    stage(0, 0); CP_COMMIT();
    stage(1, 1); CP_COMMIT();

    int buf = 0;

    for (int c = 0; c < NC; c++) {
        CP_WAIT(1);
        __syncthreads();

        uint32_t abase = sbase + (buf * STAGE_WORDS) * 4;
        uint32_t bbase = abase + A_WORDS * 4;
        uint32_t a_tile = abase + (uint32_t)(wm * 32 * SPAD * 4) + a_lane;
        uint32_t b_tile = bbase + (uint32_t)(wn * 64 * SPAD * 4) + b_lane;

        #pragma unroll
        for (int k16 = 0; k16 < 4; k16++) {      // 4 k16 steps per 64-half chunk
            uint32_t koff = (uint32_t)(k16 * 32);   // 8 words = 32 bytes per step
            uint32_t af[2][4], bf[8][2];
            #pragma unroll
            for (int i = 0; i < 2; i++) {
                LDMX4(af[i][0], af[i][1], af[i][2], af[i][3],
                      a_tile + (uint32_t)(i * 16 * SPAD * 4) + koff);
            }
            #pragma unroll
            for (int j2 = 0; j2 < 4; j2++) {
                LDMX4(bf[2 * j2][0], bf[2 * j2][1], bf[2 * j2 + 1][0], bf[2 * j2 + 1][1],
                      b_tile + (uint32_t)(j2 * 16 * SPAD * 4) + koff);
            }
            #pragma unroll
            for (int i = 0; i < 2; i++)
                #pragma unroll
                for (int j = 0; j < 8; j++)
                    mma_f16(acc[i][j], af[i], bf[j], acc[i][j]);
        }

        if (c + 2 < NC) {
            int nb = buf + 2; if (nb >= NSTAGE) nb -= NSTAGE;
            stage(c + 2, nb);
            CP_COMMIT();
        } else {
            CP_COMMIT();
        }
        buf = (buf + 1 == NSTAGE) ? 0 : buf + 1;
    }

    // ---- epilogue ----
    float hs[4][7];
    if (HEADS) {
        #pragma unroll
        for (int sl = 0; sl < 4; sl++)
            #pragma unroll
            for (int o = 0; o < 7; o++) hs[sl][o] = 0.f;
    }

    #pragma unroll
    for (int i = 0; i < 2; i++) {
        int m = m0 + wm * 32 + i * 16 + g;
        bool ok0 = (m < M), ok1 = (m + 8 < M);
        #pragma unroll
        for (int j = 0; j < 8; j++) {
            int n = wn * 64 + j * 8 + 2 * tg;
            float bx = bias[n], by = bias[n + 1];
            float v0 = acc[i][j][0] + bx, v1 = acc[i][j][1] + by;
            float w0 = acc[i][j][2] + bx, w1 = acc[i][j][3] + by;
            if (RELU) {
                v0 = fmaxf(v0, 0.f); v1 = fmaxf(v1, 0.f);
                w0 = fmaxf(w0, 0.f); w1 = fmaxf(w1, 0.f);
            }
            if (STOREF) {
                if (ok0) *reinterpret_cast<float2*>(C + (size_t)m * 256 + n) = make_float2(v0, v1);
                if (ok1) *reinterpret_cast<float2*>(C + (size_t)(m + 8) * 256 + n) = make_float2(w0, w1);
            }
            if (STOREH) {
                if (ok0) *reinterpret_cast<__half2*>(Ch + (size_t)m * 256 + n) = __floats2half2_rn(v0, v1);
                if (ok1) *reinterpret_cast<__half2*>(Ch + (size_t)(m + 8) * 256 + n) = __floats2half2_rn(w0, w1);
            }
            if (HEADS) {
                #pragma unroll
                for (int o = 0; o < 7; o++) {
                    float wa = whs[o * 256 + n], wb = whs[o * 256 + n + 1];
                    if (ok0) hs[i * 2 + 0][o] += v0 * wa + v1 * wb;
                    if (ok1) hs[i * 2 + 1][o] += w0 * wa + w1 * wb;
                }
            }
        }
    }

    if (HEADS) {
        #pragma unroll
        for (int sl = 0; sl < 4; sl++)
            #pragma unroll
            for (int o = 0; o < 7; o++) {
                float v = hs[sl][o];
                v += __shfl_xor_sync(0xffffffffu, v, 1);
                v += __shfl_xor_sync(0xffffffffu, v, 2);
                hs[sl][o] = v;
            }
        if (tg == 0) {
            #pragma unroll
            for (int sl = 0; sl < 4; sl++) {
                int i = sl >> 1, h = sl & 1;
                int row = wm * 32 + i * 16 + g + h * 8;
                #pragma unroll
                for (int o = 0; o < 7; o++)
                    part[(wn * 128 + row) * 7 + o] = hs[sl][o];
            }
        }
        __syncthreads();
        if (tid < 128) {
            int m = m0 + tid;
            if (m < M) {
                #pragma unroll
                for (int o = 0; o < 7; o++) {
                    float v = part[(0 * 128 + tid) * 7 + o] + part[(1 * 128 + tid) * 7 + o]
                            + part[(2 * 128 + tid) * 7 + o] + part[(3 * 128 + tid) * 7 + o];
                    if (o < 4) out1[(size_t)m * 4 + o] = v + bh1[o];
                    else       out2[(size_t)m * 3 + (o - 4)] = v + bh2[o - 4];
                }
            }
        }
    }
}

// ---------------- launch ----------------
extern "C" void kernel_launch(void* const* d_in, const int* in_sizes, int n_in,
                              void* d_out, int out_size) {
    const float* x   = (const float*)d_in[0];
    const int*   ei  = (const int*)  d_in[1];
    const float* W1l = (const float*)d_in[2];
    const float* b1l = (const float*)d_in[3];
    const float* W1r = (const float*)d_in[4];
    const float* W2l = (const float*)d_in[5];
    const float* b2l = (const float*)d_in[6];
    const float* W2r = (const float*)d_in[7];
    const float* Wh1 = (const float*)d_in[8];
    const float* bh1 = (const float*)d_in[9];
    const float* Wh2 = (const float*)d_in[10];
    const float* bh2 = (const float*)d_in[11];

    float* out  = (float*)d_out;
    float* out1 = out;                                  // [N,4]
    float* out2 = out + (size_t)N_NODES * 4;            // [N,3]
    float* hout = out + (size_t)N_NODES * 7;            // [N,256]

    const int* src = ei;             // edge_index[0]
    const int* dst = ei + N_EDGES;   // edge_index[1]

    void *p_xh, *p_h1h, *p_agg1h, *p_agg2h, *p_wrh;
    cudaGetSymbolAddress(&p_xh,    g_xh);
    cudaGetSymbolAddress(&p_h1h,   g_h1h);
    cudaGetSymbolAddress(&p_agg1h, g_agg1h);
    cudaGetSymbolAddress(&p_agg2h, g_agg2h);
    cudaGetSymbolAddress(&p_wrh,   g_wrh);
    const __half* wrh = (const __half*)p_wrh;

    cudaFuncSetAttribute(gemm_h<true, false, false, true>,
                         cudaFuncAttributeMaxDynamicSharedMemorySize, GEMM_SMEM_BYTES);
    cudaFuncSetAttribute(gemm_h<false, true, true, false>,
                         cudaFuncAttributeMaxDynamicSharedMemorySize, GEMM2_SMEM_BYTES);

    prep_count<<<(XN4 + WN4 + EN8 + 255) / 256, 256>>>(x, W1l, W1r, W2l, W2r, dst);
    scan1_kernel<<<SCAN_BLOCKS, 256>>>();
    scan2_kernel<<<SCAN_BLOCKS, 256>>>();
    fill_kernel<<<(N_EDGES / 8 + 255) / 256, 256>>>(src, dst);

    int gtiles = (N_NODES + GBM - 1) / GBM;   // 391

    // layer 1: h1 = relu(agg1 @ W1l^T + x @ W1r^T + b1l)  [h1 stored fp16 only]
    agg_kernel_h<1><<<(N_NODES + 7) / 8, 256>>>((const __half*)p_xh, (__half*)p_agg1h);
    gemm_h<true, false, false, true><<<gtiles, GTHREADS, GEMM_SMEM_BYTES>>>(
        (const __half*)p_agg1h, wrh + W1L_OFF, F_IN, (const __half*)p_xh, wrh + W1R_OFF, F_IN,
        b1l, nullptr, N_NODES, (__half*)p_h1h,
        nullptr, nullptr, nullptr, nullptr, nullptr, nullptr);

    // layer 2 + heads: hout = agg2 @ W2l^T + h1 @ W2r^T + b2l; out1/out2 fused
    agg_kernel_h<2><<<(N_NODES + 7) / 8, 256>>>((const __half*)p_h1h, (__half*)p_agg2h);
    gemm_h<false, true, true, false><<<gtiles, GTHREADS, GEMM2_SMEM_BYTES>>>(
        (const __half*)p_agg2h, wrh + W2L_OFF, HID, (const __half*)p_h1h, wrh + W2R_OFF, HID,
        b2l, hout, N_NODES, nullptr,
        Wh1, bh1, Wh2, bh2, out1, out2);
}

// round 17
// speedup vs baseline: 1.0910x; 1.0002x over previous
#include <cuda_runtime.h>
#include <cuda_fp16.h>
#include <cstdint>

#define N_NODES 50000
#define N_EDGES 800000
#define F_IN    128
#define HID     256

// ---------------- scratch (device globals; no allocation allowed) ----------------
// INVARIANTS at kernel_launch entry (zero-init at load, restored each replay):
//   g_deg == 0  (scan1 re-zeros after reading)
//   g_cur is rebuilt by scan2 every replay (holds insertion cursors = g_off copies)
__device__ int    g_deg[N_NODES];
__device__ int    g_off[N_NODES + 1];
__device__ int    g_cur[N_NODES];
__device__ int    g_csr[N_EDGES];
__device__ int    g_bsum[256];
__device__ __half g_xh   [(size_t)N_NODES * F_IN];   // fp16 x
__device__ __half g_h1h  [(size_t)N_NODES * HID];    // fp16 h1
__device__ __half g_agg1h[(size_t)N_NODES * F_IN];   // fp16 agg1
__device__ __half g_agg2h[(size_t)N_NODES * HID];    // fp16 agg2
__device__ __half g_wrh  [196608];                   // fp16 W1l|W1r|W2l|W2r

#define W1L_OFF 0
#define W1R_OFF 32768
#define W2L_OFF 65536
#define W2R_OFF 131072

// ---------------- prep (x+weights -> fp16) fused with edge count (8 edges/thread) ----------------
#define XN4 ((N_NODES * F_IN) / 4)      // 1,600,000
#define WN4 (196608 / 4)                // 49,152
#define EN8 (N_EDGES / 8)               // 100,000
__global__ void prep_count(const float* __restrict__ x,
                           const float* __restrict__ w1l, const float* __restrict__ w1r,
                           const float* __restrict__ w2l, const float* __restrict__ w2r,
                           const int* __restrict__ dst) {
    int i = blockIdx.x * blockDim.x + threadIdx.x;
    if (i < XN4) {
        float4 v = reinterpret_cast<const float4*>(x)[i];
        __half2 h0 = __floats2half2_rn(v.x, v.y);
        __half2 h1 = __floats2half2_rn(v.z, v.w);
        uint2 hu;
        hu.x = *reinterpret_cast<uint32_t*>(&h0);
        hu.y = *reinterpret_cast<uint32_t*>(&h1);
        reinterpret_cast<uint2*>(g_xh)[i] = hu;
        return;
    }
    int j = i - XN4;
    if (j < WN4) {
        int e = j * 4;
        const float* s;
        if      (e < W1R_OFF) s = w1l + (e - W1L_OFF);
        else if (e < W2L_OFF) s = w1r + (e - W1R_OFF);
        else if (e < W2R_OFF) s = w2l + (e - W2L_OFF);
        else                  s = w2r + (e - W2R_OFF);
        float4 v = *reinterpret_cast<const float4*>(s);
        __half2 h0 = __floats2half2_rn(v.x, v.y);
        __half2 h1 = __floats2half2_rn(v.z, v.w);
        uint2 hu;
        hu.x = *reinterpret_cast<uint32_t*>(&h0);
        hu.y = *reinterpret_cast<uint32_t*>(&h1);
        reinterpret_cast<uint2*>(g_wrh)[j] = hu;
        return;
    }
    int t = j - WN4;
    if (t >= EN8) return;
    int e0 = t * 8;                                       // N_EDGES % 8 == 0
    int4 d0 = *reinterpret_cast<const int4*>(dst + e0);
    int4 d1 = *reinterpret_cast<const int4*>(dst + e0 + 4);
    atomicAdd(&g_deg[d0.x], 1); atomicAdd(&g_deg[d0.y], 1);
    atomicAdd(&g_deg[d0.z], 1); atomicAdd(&g_deg[d0.w], 1);
    atomicAdd(&g_deg[d1.x], 1); atomicAdd(&g_deg[d1.y], 1);
    atomicAdd(&g_deg[d1.z], 1); atomicAdd(&g_deg[d1.w], 1);
}

#define SCAN_BLOCKS 196
__device__ __forceinline__ int warp_incl_scan(int v, int lane) {
    #pragma unroll
    for (int o = 1; o < 32; o <<= 1) {
        int t = __shfl_up_sync(0xffffffffu, v, o);
        if (lane >= o) v += t;
    }
    return v;
}

__global__ void scan1_kernel() {   // local exclusive scan + block sums; re-zeros g_deg
    __shared__ int ws[8];
    int tid = threadIdx.x, lane = tid & 31, w = tid >> 5;
    int i = blockIdx.x * 256 + tid;
    int v = (i < N_NODES) ? g_deg[i] : 0;
    if (i < N_NODES) g_deg[i] = 0;
    int inc = warp_incl_scan(v, lane);
    if (lane == 31) ws[w] = inc;
    __syncthreads();
    if (w == 0) {
        int t = (lane < 8) ? ws[lane] : 0;
        t = warp_incl_scan(t, lane);
        if (lane < 8) ws[lane] = t;
    }
    __syncthreads();
    int base = (w > 0) ? ws[w - 1] : 0;
    if (i < N_NODES) g_off[i] = base + inc - v;
    if (tid == 255) g_bsum[blockIdx.x] = ws[7];
}

__global__ void scan2_kernel() {   // merged spine-reduce + add-back; seeds g_cur cursors
    __shared__ int ws[8];
    int tid = threadIdx.x, lane = tid & 31, w = tid >> 5;
    int bid = blockIdx.x;
    int v = (tid < bid) ? g_bsum[tid] : 0;
    #pragma unroll
    for (int o = 16; o > 0; o >>= 1) v += __shfl_xor_sync(0xffffffffu, v, o);
    if (lane == 0) ws[w] = v;
    __syncthreads();
    int base = ws[0] + ws[1] + ws[2] + ws[3] + ws[4] + ws[5] + ws[6] + ws[7];
    int i = bid * 256 + tid;
    if (i < N_NODES) {
        int nv = g_off[i] + base;
        g_off[i] = nv;
        g_cur[i] = nv;       // fill's insertion cursor starts at the segment base
    }
    if (bid == SCAN_BLOCKS - 1 && tid == 0)
        g_off[N_NODES] = base + g_bsum[SCAN_BLOCKS - 1];
}

// one atomic per edge: cursor carries the offset
__global__ void fill_kernel(const int* __restrict__ src, const int* __restrict__ dst) {
    int t = blockIdx.x * blockDim.x + threadIdx.x;
    int e0 = t * 4;
    if (e0 >= N_EDGES) return;
    int4 d = *reinterpret_cast<const int4*>(dst + e0);
    int4 s = *reinterpret_cast<const int4*>(src + e0);
    g_csr[atomicAdd(&g_cur[d.x], 1)] = s.x;
    g_csr[atomicAdd(&g_cur[d.y], 1)] = s.y;
    g_csr[atomicAdd(&g_cur[d.z], 1)] = s.z;
    g_csr[atomicAdd(&g_cur[d.w], 1)] = s.w;
}

// ---------------- mean aggregation (fp16 gather -> fp16 out) ----------------
template <int SL>
__global__ void agg_kernel_h(const __half* __restrict__ feat, __half* __restrict__ out) {
    constexpr int F = SL * 128;
    int node = blockIdx.x * (blockDim.x >> 5) + (threadIdx.x >> 5);
    if (node >= N_NODES) return;
    int lane = threadIdx.x & 31;
    int col = lane * (4 * SL);     // 4 or 8 halfs per lane

    float a[4][4 * SL];
    #pragma unroll
    for (int k = 0; k < 4; k++)
        #pragma unroll
        for (int q = 0; q < 4 * SL; q++) a[k][q] = 0.f;

    int s = g_off[node], e = g_off[node + 1];
    int i = s;
    for (; i + 3 < e; i += 4) {
        int idx[4];
        #pragma unroll
        for (int k = 0; k < 4; k++) idx[k] = g_csr[i + k];
        #pragma unroll
        for (int k = 0; k < 4; k++) {
            if (SL == 1) {
                uint2 u = *reinterpret_cast<const uint2*>(feat + (size_t)idx[k] * F + col);
                float2 f0 = __half22float2(*reinterpret_cast<__half2*>(&u.x));
                float2 f1 = __half22float2(*reinterpret_cast<__half2*>(&u.y));
                a[k][0] += f0.x; a[k][1] += f0.y; a[k][2] += f1.x; a[k][3] += f1.y;
            } else {
                uint4 u = *reinterpret_cast<const uint4*>(feat + (size_t)idx[k] * F + col);
                float2 f0 = __half22float2(*reinterpret_cast<__half2*>(&u.x));
                float2 f1 = __half22float2(*reinterpret_cast<__half2*>(&u.y));
                float2 f2 = __half22float2(*reinterpret_cast<__half2*>(&u.z));
                float2 f3 = __half22float2(*reinterpret_cast<__half2*>(&u.w));
                a[k][0] += f0.x; a[k][1] += f0.y; a[k][2] += f1.x; a[k][3] += f1.y;
                a[k][4] += f2.x; a[k][5] += f2.y; a[k][6] += f3.x; a[k][7] += f3.y;
            }
        }
    }
    for (; i < e; i++) {
        int s0 = g_csr[i];
        if (SL == 1) {
            uint2 u = *reinterpret_cast<const uint2*>(feat + (size_t)s0 * F + col);
            float2 f0 = __half22float2(*reinterpret_cast<__half2*>(&u.x));
            float2 f1 = __half22float2(*reinterpret_cast<__half2*>(&u.y));
            a[0][0] += f0.x; a[0][1] += f0.y; a[0][2] += f1.x; a[0][3] += f1.y;
        } else {
            uint4 u = *reinterpret_cast<const uint4*>(feat + (size_t)s0 * F + col);
            float2 f0 = __half22float2(*reinterpret_cast<__half2*>(&u.x));
            float2 f1 = __half22float2(*reinterpret_cast<__half2*>(&u.y));
            float2 f2 = __half22float2(*reinterpret_cast<__half2*>(&u.z));
            float2 f3 = __half22float2(*reinterpret_cast<__half2*>(&u.w));
            a[0][0] += f0.x; a[0][1] += f0.y; a[0][2] += f1.x; a[0][3] += f1.y;
            a[0][4] += f2.x; a[0][5] += f2.y; a[0][6] += f3.x; a[0][7] += f3.y;
        }
    }
    float inv = (e > s) ? 1.0f / (float)(e - s) : 0.0f;
    if (SL == 1) {
        __half2 o0 = __floats2half2_rn((a[0][0] + a[1][0] + a[2][0] + a[3][0]) * inv,
                                       (a[0][1] + a[1][1] + a[2][1] + a[3][1]) * inv);
        __half2 o1 = __floats2half2_rn((a[0][2] + a[1][2] + a[2][2] + a[3][2]) * inv,
                                       (a[0][3] + a[1][3] + a[2][3] + a[3][3]) * inv);
        uint2 ou;
        ou.x = *reinterpret_cast<uint32_t*>(&o0);
        ou.y = *reinterpret_cast<uint32_t*>(&o1);
        *reinterpret_cast<uint2*>(out + (size_t)node * F + col) = ou;
    } else {
        uint4 ou;
        #pragma unroll
        for (int p = 0; p < 4; p++) {
            __half2 h = __floats2half2_rn(
                (a[0][2 * p] + a[1][2 * p] + a[2][2 * p] + a[3][2 * p]) * inv,
                (a[0][2 * p + 1] + a[1][2 * p + 1] + a[2][2 * p + 1] + a[3][2 * p + 1]) * inv);
            (&ou.x)[p] = *reinterpret_cast<uint32_t*>(&h);
        }
        *reinterpret_cast<uint4*>(out + (size_t)node * F + col) = ou;
    }
}

// ======================= fp16 m16n8k16 dual GEMM (+fused heads, ldmatrix, BK=64) =======================
#define GBM 128
#define GBN 256
#define GBK 64               // halfs per chunk (128B rows)
#define SPAD 36              // smem row stride in 32-bit words (32 data + 4 pad)
#define GTHREADS 512
#define NSTAGE 3

#define A_WORDS (GBM * SPAD)                   // 4608
#define B_WORDS (GBN * SPAD)                   // 9216
#define STAGE_WORDS (A_WORDS + B_WORDS)        // 13824
#define WH_WORDS 1792
#define PART_WORDS (4 * 128 * 7)
#define GEMM_SMEM_BYTES  (NSTAGE * STAGE_WORDS * 4)                            // 165888
#define GEMM2_SMEM_BYTES ((NSTAGE * STAGE_WORDS + WH_WORDS + PART_WORDS) * 4)  // 187392

__device__ __forceinline__ void mma_f16(float* d, const uint32_t* a, const uint32_t* b,
                                        const float* c) {
    asm volatile(
        "mma.sync.aligned.m16n8k16.row.col.f32.f16.f16.f32 "
        "{%0,%1,%2,%3}, {%4,%5,%6,%7}, {%8,%9}, {%10,%11,%12,%13};"
        : "=f"(d[0]), "=f"(d[1]), "=f"(d[2]), "=f"(d[3])
        : "r"(a[0]), "r"(a[1]), "r"(a[2]), "r"(a[3]),
          "r"(b[0]), "r"(b[1]),
          "f"(c[0]), "f"(c[1]), "f"(c[2]), "f"(c[3]));
}

#define LDMX4(r0, r1, r2, r3, addr) \
    asm volatile("ldmatrix.sync.aligned.m8n8.x4.shared.b16 {%0,%1,%2,%3}, [%4];" \
        : "=r"(r0), "=r"(r1), "=r"(r2), "=r"(r3) : "r"(addr))

__device__ __forceinline__ void cp16(uint32_t dst, const void* src, bool ok) {
    int sz = ok ? 16 : 0;
    asm volatile("cp.async.cg.shared.global [%0], [%1], 16, %2;"
                 :: "r"(dst), "l"(src), "r"(sz));
}
#define CP_COMMIT() asm volatile("cp.async.commit_group;" ::: "memory")
#define CP_WAIT(n)  asm volatile("cp.async.wait_group %0;" :: "n"(n) : "memory")

template <bool RELU, bool HEADS, bool STOREF, bool STOREH>
__global__ __launch_bounds__(GTHREADS)
void gemm_h(const __half* __restrict__ A1, const __half* __restrict__ B1, int K1,
            const __half* __restrict__ A2, const __half* __restrict__ B2, int K2,
            const float* __restrict__ bias, float* __restrict__ C, int M,
            __half* __restrict__ Ch,
            const float* __restrict__ Wh1, const float* __restrict__ bh1,
            const float* __restrict__ Wh2, const float* __restrict__ bh2,
            float* __restrict__ out1, float* __restrict__ out2) {
    extern __shared__ float gsm[];
    uint32_t sbase;
    asm("{ .reg .u64 t; cvta.to.shared.u64 t, %1; cvt.u32.u64 %0, t; }"
        : "=r"(sbase) : "l"(gsm));

    int tid  = threadIdx.x;
    int wid  = tid >> 5;
    int lane = tid & 31;
    int wm   = wid & 3;
    int wn   = wid >> 2;
    int g    = lane >> 2;
    int tg   = lane & 3;

    int m0 = blockIdx.x * GBM;

    // ldmatrix lane addressing (bytes, relative to tile base at k-word 0):
    int quad = lane >> 3, r = lane & 7;
    uint32_t a_lane = (uint32_t)((((quad & 1) ? 8 : 0) + r) * SPAD * 4 + (quad >> 1) * 16);
    uint32_t b_lane = (uint32_t)((((quad >> 1) ? 8 : 0) + r) * SPAD * 4 + (quad & 1) * 16);

    float* whs  = gsm + NSTAGE * STAGE_WORDS;
    float* part = whs + WH_WORDS;
    if (HEADS) {
        for (int idx = tid; idx < WH_WORDS; idx += GTHREADS) {
            int o = idx >> 8, cc = idx & 255;
            whs[idx] = (o < 4) ? Wh1[o * 256 + cc] : Wh2[(o - 4) * 256 + cc];
        }
    }

    const int NC1 = K1 / GBK;
    const int NC  = NC1 + K2 / GBK;   // 4 (gemm1) or 8 (gemm2)

    float acc[2][8][4];
    #pragma unroll
    for (int i = 0; i < 2; i++)
        #pragma unroll
        for (int j = 0; j < 8; j++)
            #pragma unroll
            for (int q = 0; q < 4; q++) acc[i][j][q] = 0.f;

    auto stage = [&](int c, int buf) {
        const __half* A; const __half* B; int K, k0;
        if (c < NC1) { A = A1; B = B1; K = K1; k0 = c * GBK; }
        else         { A = A2; B = B2; K = K2; k0 = (c - NC1) * GBK; }
        uint32_t abase = sbase + (buf * STAGE_WORDS) * 4;
        uint32_t bbase = abase + A_WORDS * 4;
        #pragma unroll
        for (int l = 0; l < 2; l++) {
            int idx = tid + l * GTHREADS;
            int row = idx >> 3;
            int q   = idx & 7;          // 16B unit within 128B row
            cp16(abase + (row * SPAD + q * 4) * 4,
                 A + (size_t)(m0 + row) * K + k0 + q * 8,
                 (m0 + row) < M);
        }
        #pragma unroll
        for (int l = 0; l < 4; l++) {
            int idx = tid + l * GTHREADS;
            int row = idx >> 3;
            int q   = idx & 7;
            cp16(bbase + (row * SPAD + q * 4) * 4,
                 B + (size_t)row * K + k0 + q * 8, true);
        }
    };

    stage(0, 0); CP_COMMIT();
    stage(1, 1); CP_COMMIT();

    int buf = 0;

    for (int c = 0; c < NC; c++) {
        CP_WAIT(1);
        __syncthreads();

        uint32_t abase = sbase + (buf * STAGE_WORDS) * 4;
        uint32_t bbase = abase + A_WORDS * 4;
        uint32_t a_tile = abase + (uint32_t)(wm * 32 * SPAD * 4) + a_lane;
        uint32_t b_tile = bbase + (uint32_t)(wn * 64 * SPAD * 4) + b_lane;

        #pragma unroll
        for (int k16 = 0; k16 < 4; k16++) {      // 4 k16 steps per 64-half chunk
            uint32_t koff = (uint32_t)(k16 * 32);   // 8 words = 32 bytes per step
            uint32_t af[2][4], bf[8][2];
            #pragma unroll
            for (int i = 0; i < 2; i++) {
                LDMX4(af[i][0], af[i][1], af[i][2], af[i][3],
                      a_tile + (uint32_t)(i * 16 * SPAD * 4) + koff);
            }
            #pragma unroll
            for (int j2 = 0; j2 < 4; j2++) {
                LDMX4(bf[2 * j2][0], bf[2 * j2][1], bf[2 * j2 + 1][0], bf[2 * j2 + 1][1],
                      b_tile + (uint32_t)(j2 * 16 * SPAD * 4) + koff);
            }
            #pragma unroll
            for (int i = 0; i < 2; i++)
                #pragma unroll
                for (int j = 0; j < 8; j++)
                    mma_f16(acc[i][j], af[i], bf[j], acc[i][j]);
        }

        if (c + 2 < NC) {
            int nb = buf + 2; if (nb >= NSTAGE) nb -= NSTAGE;
            stage(c + 2, nb);
            CP_COMMIT();
        } else {
            CP_COMMIT();
        }
        buf = (buf + 1 == NSTAGE) ? 0 : buf + 1;
    }

    // ---- epilogue ----
    float hs[4][7];
    if (HEADS) {
        #pragma unroll
        for (int sl = 0; sl < 4; sl++)
            #pragma unroll
            for (int o = 0; o < 7; o++) hs[sl][o] = 0.f;
    }

    #pragma unroll
    for (int i = 0; i < 2; i++) {
        int m = m0 + wm * 32 + i * 16 + g;
        bool ok0 = (m < M), ok1 = (m + 8 < M);
        #pragma unroll
        for (int j = 0; j < 8; j++) {
            int n = wn * 64 + j * 8 + 2 * tg;
            float bx = bias[n], by = bias[n + 1];
            float v0 = acc[i][j][0] + bx, v1 = acc[i][j][1] + by;
            float w0 = acc[i][j][2] + bx, w1 = acc[i][j][3] + by;
            if (RELU) {
                v0 = fmaxf(v0, 0.f); v1 = fmaxf(v1, 0.f);
                w0 = fmaxf(w0, 0.f); w1 = fmaxf(w1, 0.f);
            }
            if (STOREF) {
                if (ok0) *reinterpret_cast<float2*>(C + (size_t)m * 256 + n) = make_float2(v0, v1);
                if (ok1) *reinterpret_cast<float2*>(C + (size_t)(m + 8) * 256 + n) = make_float2(w0, w1);
            }
            if (STOREH) {
                if (ok0) *reinterpret_cast<__half2*>(Ch + (size_t)m * 256 + n) = __floats2half2_rn(v0, v1);
                if (ok1) *reinterpret_cast<__half2*>(Ch + (size_t)(m + 8) * 256 + n) = __floats2half2_rn(w0, w1);
            }
            if (HEADS) {
                #pragma unroll
                for (int o = 0; o < 7; o++) {
                    float wa = whs[o * 256 + n], wb = whs[o * 256 + n + 1];
                    if (ok0) hs[i * 2 + 0][o] += v0 * wa + v1 * wb;
                    if (ok1) hs[i * 2 + 1][o] += w0 * wa + w1 * wb;
                }
            }
        }
    }

    if (HEADS) {
        #pragma unroll
        for (int sl = 0; sl < 4; sl++)
            #pragma unroll
            for (int o = 0; o < 7; o++) {
                float v = hs[sl][o];
                v += __shfl_xor_sync(0xffffffffu, v, 1);
                v += __shfl_xor_sync(0xffffffffu, v, 2);
                hs[sl][o] = v;
            }
        if (tg == 0) {
            #pragma unroll
            for (int sl = 0; sl < 4; sl++) {
                int i = sl >> 1, h = sl & 1;
                int row = wm * 32 + i * 16 + g + h * 8;
                #pragma unroll
                for (int o = 0; o < 7; o++)
                    part[(wn * 128 + row) * 7 + o] = hs[sl][o];
            }
        }
        __syncthreads();
        if (tid < 128) {
            int m = m0 + tid;
            if (m < M) {
                #pragma unroll
                for (int o = 0; o < 7; o++) {
                    float v = part[(0 * 128 + tid) * 7 + o] + part[(1 * 128 + tid) * 7 + o]
                            + part[(2 * 128 + tid) * 7 + o] + part[(3 * 128 + tid) * 7 + o];
                    if (o < 4) out1[(size_t)m * 4 + o] = v + bh1[o];
                    else       out2[(size_t)m * 3 + (o - 4)] = v + bh2[o - 4];
                }
            }
        }
    }
}

// ---------------- launch ----------------
extern "C" void kernel_launch(void* const* d_in, const int* in_sizes, int n_in,
                              void* d_out, int out_size) {
    const float* x   = (const float*)d_in[0];
    const int*   ei  = (const int*)  d_in[1];
    const float* W1l = (const float*)d_in[2];
    const float* b1l = (const float*)d_in[3];
    const float* W1r = (const float*)d_in[4];
    const float* W2l = (const float*)d_in[5];
    const float* b2l = (const float*)d_in[6];
    const float* W2r = (const float*)d_in[7];
    const float* Wh1 = (const float*)d_in[8];
    const float* bh1 = (const float*)d_in[9];
    const float* Wh2 = (const float*)d_in[10];
    const float* bh2 = (const float*)d_in[11];

    float* out  = (float*)d_out;
    float* out1 = out;                                  // [N,4]
    float* out2 = out + (size_t)N_NODES * 4;            // [N,3]
    float* hout = out + (size_t)N_NODES * 7;            // [N,256]

    const int* src = ei;             // edge_index[0]
    const int* dst = ei + N_EDGES;   // edge_index[1]

    void *p_xh, *p_h1h, *p_agg1h, *p_agg2h, *p_wrh;
    cudaGetSymbolAddress(&p_xh,    g_xh);
    cudaGetSymbolAddress(&p_h1h,   g_h1h);
    cudaGetSymbolAddress(&p_agg1h, g_agg1h);
    cudaGetSymbolAddress(&p_agg2h, g_agg2h);
    cudaGetSymbolAddress(&p_wrh,   g_wrh);
    const __half* wrh = (const __half*)p_wrh;

    cudaFuncSetAttribute(gemm_h<true, false, false, true>,
                         cudaFuncAttributeMaxDynamicSharedMemorySize, GEMM_SMEM_BYTES);
    cudaFuncSetAttribute(gemm_h<false, true, true, false>,
                         cudaFuncAttributeMaxDynamicSharedMemorySize, GEMM2_SMEM_BYTES);

    prep_count<<<(XN4 + WN4 + EN8 + 255) / 256, 256>>>(x, W1l, W1r, W2l, W2r, dst);
    scan1_kernel<<<SCAN_BLOCKS, 256>>>();
    scan2_kernel<<<SCAN_BLOCKS, 256>>>();
    fill_kernel<<<(N_EDGES / 4 + 255) / 256, 256>>>(src, dst);

    int gtiles = (N_NODES + GBM - 1) / GBM;   // 391

    // layer 1: h1 = relu(agg1 @ W1l^T + x @ W1r^T + b1l)  [h1 stored fp16 only]
    agg_kernel_h<1><<<(N_NODES + 7) / 8, 256>>>((const __half*)p_xh, (__half*)p_agg1h);
    gemm_h<true, false, false, true><<<gtiles, GTHREADS, GEMM_SMEM_BYTES>>>(
        (const __half*)p_agg1h, wrh + W1L_OFF, F_IN, (const __half*)p_xh, wrh + W1R_OFF, F_IN,
        b1l, nullptr, N_NODES, (__half*)p_h1h,
        nullptr, nullptr, nullptr, nullptr, nullptr, nullptr);

    // layer 2 + heads: hout = agg2 @ W2l^T + h1 @ W2r^T + b2l; out1/out2 fused
    agg_kernel_h<2><<<(N_NODES + 7) / 8, 256>>>((const __half*)p_h1h, (__half*)p_agg2h);
    gemm_h<false, true, true, false><<<gtiles, GTHREADS, GEMM2_SMEM_BYTES>>>(
        (const __half*)p_agg2h, wrh + W2L_OFF, HID, (const __half*)p_h1h, wrh + W2R_OFF, HID,
        b2l, hout, N_NODES, nullptr,
        Wh1, bh1, Wh2, bh2, out1, out2);
}